// round 12
// baseline (speedup 1.0000x reference)
#include <cuda_runtime.h>
#include <cuda_fp16.h>
#include <cstdint>
#include <math_constants.h>

// Problem constants (fixed by the dataset)
#define NN 100000
#define EE 1000000
#define NREL 7
#define CAP 16          // max edges per (dst,rel) segment; Poisson(1.43), max over 700K segs ~ 12
#define TN 128          // nodes per tile in transform1 (8 warps x 16 nodes)

// ---------------- scratch (device globals; no allocation allowed) ----------------
__device__ int     g_cnt[NN * NREL];                     // 2.8 MB  per-(dst,rel) edge count
__device__ int     g_bucket[(size_t)NN * NREL * CAP];    // 44.8 MB src per segment slot
__device__ __half2 g_yh[(size_t)NREL * NN * 32];         // 89.6 MB y[r][node] = x@W1[r] (fp16)
__device__ float   g_z[(size_t)NN * 16];                 // 6.4 MB  z[node][r*2+ch] (node-major)
__device__ float   g_hbase[(size_t)NN * 64];             // x @ root1 + bias1

// ---------------- mma helper (m16n8k16 fp16 -> f32) ----------------
__device__ __forceinline__ void mma16816(float& d0, float& d1, float& d2, float& d3,
                                         uint32_t a0, uint32_t a1, uint32_t a2, uint32_t a3,
                                         uint32_t b0, uint32_t b1) {
    asm volatile(
        "mma.sync.aligned.m16n8k16.row.col.f32.f16.f16.f32 "
        "{%0,%1,%2,%3}, {%4,%5,%6,%7}, {%8,%9}, {%0,%1,%2,%3};"
        : "+f"(d0), "+f"(d1), "+f"(d2), "+f"(d3)
        : "r"(a0), "r"(a1), "r"(a2), "r"(a3), "r"(b0), "r"(b1));
}

// ---------------- small kernels ----------------
__global__ void zero_cnt_kernel(int n7q) {
    int i = blockIdx.x * blockDim.x + threadIdx.x;
    if (i < n7q) ((int4*)g_cnt)[i] = make_int4(0, 0, 0, 0);
}

// ---------------- mega kernel 1: scatter | dense1 | transform1 ----------------
__device__ __forceinline__ void scatter_body(const int* __restrict__ ei,
                                             const int* __restrict__ et,
                                             int n, int e, int bid) {
    int i = bid * 256 + threadIdx.x;
    if (i >= e) return;
    int dst = ei[e + i];
    int r   = et[i];
    long seg = (long)dst * NREL + r;
    int idx = atomicAdd(&g_cnt[seg], 1);
    if (idx < CAP) g_bucket[seg * CAP + idx] = ei[i];
}

__device__ __forceinline__ void dense1_body(const float* __restrict__ x,
                                            const float* __restrict__ root1,
                                            const float* __restrict__ bias1,
                                            int n, int bid, char* smem_raw) {
    float (*As)[33] = (float (*)[33])smem_raw;                 // 64 x 33 floats
    float (*Bs)[64] = (float (*)[64])(smem_raw + 64 * 33 * 4); // 32 x 64 floats
    int tid = threadIdx.x;
    int tx = tid & 15, ty = tid >> 4;
    int row0 = bid * 64;
    float acc[4][4];
#pragma unroll
    for (int i = 0; i < 4; i++)
#pragma unroll
        for (int j = 0; j < 4; j++) acc[i][j] = 0.f;

    for (int k0 = 0; k0 < 128; k0 += 32) {
        for (int t = tid; t < 512; t += 256) {          // A tile 64x32
            int m = t >> 3;
            int kk = (t & 7) << 2;
            int row = row0 + m;
            float4 v = make_float4(0.f, 0.f, 0.f, 0.f);
            if (row < n) v = *(const float4*)(x + (size_t)row * 128 + k0 + kk);
            As[m][kk] = v.x; As[m][kk + 1] = v.y; As[m][kk + 2] = v.z; As[m][kk + 3] = v.w;
        }
        for (int t = tid; t < 512; t += 256) {          // B tile 32x64
            int kk = t >> 4;
            int c4 = (t & 15) << 2;
            *(float4*)&Bs[kk][c4] = *(const float4*)(root1 + (size_t)(k0 + kk) * 64 + c4);
        }
        __syncthreads();
#pragma unroll
        for (int kk = 0; kk < 32; kk++) {
            float a0 = As[ty * 4 + 0][kk];
            float a1 = As[ty * 4 + 1][kk];
            float a2 = As[ty * 4 + 2][kk];
            float a3 = As[ty * 4 + 3][kk];
            float4 bv = *(float4*)&Bs[kk][tx * 4];
            acc[0][0] += a0 * bv.x; acc[0][1] += a0 * bv.y; acc[0][2] += a0 * bv.z; acc[0][3] += a0 * bv.w;
            acc[1][0] += a1 * bv.x; acc[1][1] += a1 * bv.y; acc[1][2] += a1 * bv.z; acc[1][3] += a1 * bv.w;
            acc[2][0] += a2 * bv.x; acc[2][1] += a2 * bv.y; acc[2][2] += a2 * bv.z; acc[2][3] += a2 * bv.w;
            acc[3][0] += a3 * bv.x; acc[3][1] += a3 * bv.y; acc[3][2] += a3 * bv.z; acc[3][3] += a3 * bv.w;
        }
        __syncthreads();
    }
    float4 bv = *(const float4*)(bias1 + tx * 4);
#pragma unroll
    for (int rr = 0; rr < 4; rr++) {
        int row = row0 + ty * 4 + rr;
        if (row < n) {
            float4 o;
            o.x = acc[rr][0] + bv.x; o.y = acc[rr][1] + bv.y;
            o.z = acc[rr][2] + bv.z; o.w = acc[rr][3] + bv.w;
            *(float4*)(g_hbase + (size_t)row * 64 + tx * 4) = o;
        }
    }
}

// Tensor-core transform: y[r][node] = x[node] @ W1[r] (block-diag), fp16 in,
// fp32 accum, fp16 out. Warp = 16 nodes; mma.m16n8k16 per (b, khalf, nhalf).
// x tile staged once as fp16 (A-frags preloaded to regs, reused for all 7 r).
// After A-preload the xs smem region is DEAD -> reused as per-warp y staging
// buffer so global y stores are fully-coalesced 128B float4 rows.
#define XS_STRIDE 68    // half2 per x row
#define WT_STRIDE 40    // halves per Wt row
#define XS_BYTES (TN * XS_STRIDE * 4)          // 34816
#define WT_OFF   XS_BYTES                      // 128B-aligned
#define YS_STRIDE 36    // half2 per staged y row (144B)

__device__ __forceinline__ void transform1_body(const float* __restrict__ x,
                                                const float* __restrict__ W1,
                                                int n, int bid, char* smem_raw) {
    __half2* xs = (__half2*)smem_raw;
    __half*  Wt = (__half*)(smem_raw + WT_OFF);
    int node0 = bid * TN;
    int tid  = threadIdx.x;
    int lane = tid & 31;
    int wid  = tid >> 5;
    int nn = min(TN, n - node0);

    // stage x tile as fp16 half2 pairs
    for (int idx = tid; idx < nn * 64; idx += 256) {
        int row = idx >> 6;
        int c   = idx & 63;
        float2 v = *(const float2*)(x + (size_t)(node0 + row) * 128 + c * 2);
        xs[row * XS_STRIDE + c] = __float22half2_rn(v);
    }
    __syncthreads();

    // preload A fragments: lane (g = lane>>2, t = lane&3)
    int g = lane >> 2;
    int t = lane & 3;
    int row0 = wid * 16;
    uint32_t A[4][2][4];
#pragma unroll
    for (int b = 0; b < 4; b++)
#pragma unroll
        for (int ks = 0; ks < 2; ks++) {
            int ci = b * 16 + ks * 8 + t;       // half2 col index
            const uint32_t* r0 = (const uint32_t*)&xs[(row0 + g) * XS_STRIDE + ci];
            const uint32_t* r1 = (const uint32_t*)&xs[(row0 + g + 8) * XS_STRIDE + ci];
            A[b][ks][0] = r0[0];
            A[b][ks][1] = r1[0];
            A[b][ks][2] = r0[4];
            A[b][ks][3] = r1[4];
        }

    // per-warp y staging buffer (aliases the now-dead xs region)
    __half2* ys = (__half2*)smem_raw + (size_t)wid * (16 * YS_STRIDE);
    int valid = min(16, nn - row0);             // nodes this warp owns (may be <=0)

    for (int r = 0; r < NREL; r++) {
        __syncthreads();   // previous relation's Wt reads done (and r=0: A-preload done)
        // stage Wt[b*16+o][i] = (half)W1[r][b][i][o]
        for (int idx = tid; idx < 2048; idx += 256) {
            int b = idx >> 9;
            int i = (idx >> 4) & 31;
            int o = idx & 15;
            float w = W1[(((size_t)r * 4 + b) * 32 + i) * 16 + o];
            Wt[(b * 16 + o) * WT_STRIDE + i] = __float2half_rn(w);
        }
        __syncthreads();

#pragma unroll
        for (int b = 0; b < 4; b++) {
#pragma unroll
            for (int nh = 0; nh < 2; nh++) {
                float d0 = 0.f, d1 = 0.f, d2 = 0.f, d3 = 0.f;
#pragma unroll
                for (int ks = 0; ks < 2; ks++) {
                    const __half* wrow = &Wt[(b * 16 + nh * 8 + g) * WT_STRIDE + ks * 16 + t * 2];
                    uint32_t b0 = *(const uint32_t*)wrow;
                    uint32_t b1 = *(const uint32_t*)(wrow + 8);
                    mma16816(d0, d1, d2, d3,
                             A[b][ks][0], A[b][ks][1], A[b][ks][2], A[b][ks][3],
                             b0, b1);
                }
                int ci = b * 8 + nh * 4 + t;
                ys[g * YS_STRIDE + ci]       = __floats2half2_rn(d0, d1);
                ys[(g + 8) * YS_STRIDE + ci] = __floats2half2_rn(d2, d3);
            }
        }
        __syncwarp();
        // coalesced copy-out: 16 rows x 128B as float4
        float4* ydst = (float4*)(g_yh + ((size_t)r * n + node0 + row0) * 32);
#pragma unroll
        for (int k = 0; k < 4; k++) {
            int idx  = k * 32 + lane;
            int rowi = idx >> 3;
            int f4   = idx & 7;
            if (rowi < valid)
                ydst[rowi * 8 + f4] =
                    *(const float4*)((const char*)ys + rowi * (YS_STRIDE * 4) + f4 * 16);
        }
        __syncwarp();
    }
}

__global__ void __launch_bounds__(256) mega1_kernel(const float* __restrict__ x,
                                                    const int* __restrict__ ei,
                                                    const int* __restrict__ et,
                                                    const float* __restrict__ W1,
                                                    const float* __restrict__ root1,
                                                    const float* __restrict__ bias1,
                                                    int n, int e,
                                                    int nScatter, int nDense) {
    __shared__ __align__(16) char smem_raw[XS_BYTES + 64 * WT_STRIDE * 2];  // ~40 KB
    int bid = blockIdx.x;
    if (bid < nScatter) {
        scatter_body(ei, et, n, e, bid);
    } else if (bid < nScatter + nDense) {
        dense1_body(x, root1, bias1, n, bid - nScatter, smem_raw);
    } else {
        transform1_body(x, W1, n, bid - nScatter - nDense, smem_raw);
    }
}

// ---------------- agg1 + transform2 + root2-partial fused ----------------
// h = relu(hbase + sum_r max_{edges(r,dst)} y[r][src])  (register-only, no store);
// z[node][r] = h @ W2[r];  out[node] = h @ root2 + bias2.
// Bucket rows read 8-wide (E[c]=1.43; c>8 tail via warp-uniform loads).
// Epilogue: multi-value butterfly, 16 totals in 16 SHFL.
__global__ void agg1_kernel(const float* __restrict__ comp2,
                            const float* __restrict__ basis2,
                            const float* __restrict__ root2,
                            const float* __restrict__ bias2,
                            float* __restrict__ out, int n) {
    __shared__ float W2s[NREL * 128];
    for (int t = threadIdx.x; t < NREL * 128; t += blockDim.x) {
        int r = t >> 7;
        int rest = t & 127;
        float v = 0.f;
#pragma unroll
        for (int bb = 0; bb < 4; bb++) v += comp2[r * 4 + bb] * basis2[bb * 128 + rest];
        W2s[t] = v;
    }
    __syncthreads();

    int node = (blockIdx.x * blockDim.x + threadIdx.x) >> 5;
    int lane = threadIdx.x & 31;
    if (node >= n) return;
    int myc = (lane < NREL) ? g_cnt[(size_t)node * NREL + lane] : 0;
    const int* bkbase = g_bucket + (size_t)node * NREL * CAP;

    // 8-wide bucket row loads (32B per segment; lanes 8..31 broadcast-duplicate)
    int row[NREL];
    int sl = lane & 7;
#pragma unroll
    for (int r = 0; r < NREL; r++) row[r] = bkbase[r * CAP + sl];

    int c[NREL];
#pragma unroll
    for (int r = 0; r < NREL; r++) c[r] = min(__shfl_sync(0xffffffffu, myc, r), CAP);

    const __half2 NEGINF2 = __float2half2_rn(-CUDART_INF_F);
    // prefetch edge 0 and edge 1 of every relation (up to 14 loads in flight)
    __half2 vA[NREL], vB[NREL];
#pragma unroll
    for (int r = 0; r < NREL; r++) {
        vA[r] = NEGINF2;
        int s0 = __shfl_sync(0xffffffffu, row[r], 0);
        if (c[r] > 0) vA[r] = g_yh[((size_t)r * n + s0) * 32 + lane];
    }
#pragma unroll
    for (int r = 0; r < NREL; r++) {
        vB[r] = NEGINF2;
        int s1 = __shfl_sync(0xffffffffu, row[r], 1);
        if (c[r] > 1) vB[r] = g_yh[((size_t)r * n + s1) * 32 + lane];
    }

    float2 v = *(const float2*)(g_hbase + (size_t)node * 64 + lane * 2);
#pragma unroll
    for (int r = 0; r < NREL; r++) {
        if (c[r] == 0) continue;
        __half2 m = vA[r];
        if (c[r] > 1) m = __hmax2(m, vB[r]);
        const __half2* yb = g_yh + (size_t)r * n * 32 + lane;
        int cr = c[r];
        for (int j = 2; j < cr; j++) {                  // rare tail (P ~ 0.17/rel)
            int s;
            if (j < 8) {
                s = __shfl_sync(0xffffffffu, row[r], j);
            } else {                                    // ultra-rare (P ~ 2e-5/seg)
                s = bkbase[r * CAP + j];                // warp-uniform broadcast load
            }
            m = __hmax2(m, yb[(size_t)s * 32]);
        }
        float2 mf = __half22float2(m);
        v.x += mf.x; v.y += mf.y;
    }
    v.x = fmaxf(v.x, 0.f);
    v.y = fmaxf(v.y, 0.f);

    // ---- per-lane partials: 16 targets = (7 rels + root) x 2 channels ----
    float p[16];
#pragma unroll
    for (int s = 0; s < NREL; s++) {
        float4 wv = *(const float4*)&W2s[s * 128 + lane * 4];
        p[s * 2]     = v.x * wv.x + v.y * wv.z;
        p[s * 2 + 1] = v.x * wv.y + v.y * wv.w;
    }
    {
        float4 rw = *(const float4*)(root2 + lane * 4);
        p[14] = v.x * rw.x + v.y * rw.z;
        p[15] = v.x * rw.y + v.y * rw.w;
    }
    // ---- multi-value butterfly: 16 totals in 16 SHFL ----
    float q8[8];
#pragma unroll
    for (int i = 0; i < 8; i++) {
        bool hi = (lane & 16) != 0;
        float send = hi ? p[i] : p[i + 8];
        float recv = __shfl_xor_sync(0xffffffffu, send, 16);
        q8[i] = (hi ? p[i + 8] : p[i]) + recv;
    }
    float q4[4];
#pragma unroll
    for (int i = 0; i < 4; i++) {
        bool hi = (lane & 8) != 0;
        float send = hi ? q8[i] : q8[i + 4];
        float recv = __shfl_xor_sync(0xffffffffu, send, 8);
        q4[i] = (hi ? q8[i + 4] : q8[i]) + recv;
    }
    float q2[2];
#pragma unroll
    for (int i = 0; i < 2; i++) {
        bool hi = (lane & 4) != 0;
        float send = hi ? q4[i] : q4[i + 2];
        float recv = __shfl_xor_sync(0xffffffffu, send, 4);
        q2[i] = (hi ? q4[i + 2] : q4[i]) + recv;
    }
    float q1;
    {
        bool hi = (lane & 2) != 0;
        float send = hi ? q2[0] : q2[1];
        float recv = __shfl_xor_sync(0xffffffffu, send, 2);
        q1 = (hi ? q2[1] : q2[0]) + recv;
    }
    q1 += __shfl_xor_sync(0xffffffffu, q1, 1);
    // lane (bit0==0) holds target: ch = (lane>>1)&1, slot = (lane>>2)&7
    if (!(lane & 1)) {
        int slot = (lane >> 2) & 7;
        int ch   = (lane >> 1) & 1;
        if (slot < NREL) {
            g_z[(size_t)node * 16 + slot * 2 + ch] = q1;   // node-major: 56B burst
        } else {
            out[(size_t)node * 2 + ch] = q1 + bias2[ch];
        }
    }
}

// out[node] += sum_r max_{edges(r,dst)} z[src][r]
// 4 nodes per warp: 8-lane groups, lane&7 = relation (lane&7==7 idle).
__global__ void final_kernel(float* __restrict__ out, int n) {
    int warp = (blockIdx.x * blockDim.x + threadIdx.x) >> 5;
    int lane = threadIdx.x & 31;
    int nl = lane >> 3;          // 0..3 node within warp
    int r  = lane & 7;           // relation (7 = idle)
    int node = warp * 4 + nl;
    float p0 = 0.f, p1 = 0.f;
    if (node < n && r < NREL) {
        size_t seg = (size_t)node * NREL + r;
        int c = min(g_cnt[seg], CAP);
        if (c > 0) {
            const int* bk = g_bucket + seg * CAP;
            float m0 = -CUDART_INF_F, m1 = -CUDART_INF_F;
            for (int j = 0; j < c; j++) {
                int src = bk[j];
                float2 zz = *(const float2*)(g_z + (size_t)src * 16 + r * 2);
                m0 = fmaxf(m0, zz.x); m1 = fmaxf(m1, zz.y);
            }
            p0 = m0; p1 = m1;
        }
    }
#pragma unroll
    for (int off = 4; off >= 1; off >>= 1) {
        p0 += __shfl_down_sync(0xffffffffu, p0, off, 8);
        p1 += __shfl_down_sync(0xffffffffu, p1, off, 8);
    }
    if (r == 0 && node < n) {
        float2 o = *(float2*)(out + (size_t)node * 2);
        o.x += p0; o.y += p1;
        *(float2*)(out + (size_t)node * 2) = o;
    }
}

// ---------------- launch ----------------
extern "C" void kernel_launch(void* const* d_in, const int* in_sizes, int n_in,
                              void* d_out, int out_size) {
    const float* x      = (const float*)d_in[0];
    const int*   ei     = (const int*)  d_in[1];
    const int*   et     = (const int*)  d_in[2];
    const float* W1     = (const float*)d_in[3];
    const float* root1  = (const float*)d_in[4];
    const float* bias1  = (const float*)d_in[5];
    const float* comp2  = (const float*)d_in[6];
    const float* basis2 = (const float*)d_in[7];
    const float* root2  = (const float*)d_in[8];
    const float* bias2  = (const float*)d_in[9];
    float* out = (float*)d_out;

    int n = in_sizes[0] / 128;   // 100000
    int e = in_sizes[2];         // 1000000

    int n7 = n * NREL;
    zero_cnt_kernel<<<(n7 / 4 + 255) / 256, 256>>>(n7 / 4);

    int nScatter = (e + 255) / 256;
    int nDense   = (n + 63) / 64;
    int nTrans   = (n + TN - 1) / TN;
    mega1_kernel<<<nScatter + nDense + nTrans, 256>>>(x, ei, et, W1, root1, bias1,
                                                      n, e, nScatter, nDense);

    int warpBlocks = (n * 32 + 255) / 256;
    agg1_kernel<<<warpBlocks, 256>>>(comp2, basis2, root2, bias2, out, n);

    int finalBlocks = ((n + 3) / 4 * 32 + 255) / 256;
    final_kernel<<<finalBlocks, 256>>>(out, n);
}

// round 13
// speedup vs baseline: 1.0726x; 1.0726x over previous
#include <cuda_runtime.h>
#include <cuda_fp16.h>
#include <cstdint>
#include <math_constants.h>

// Problem constants (fixed by the dataset)
#define NN 100000
#define EE 1000000
#define NREL 7
#define CAP 16          // max edges per (dst,rel) segment; Poisson(1.43), max over 700K segs ~ 12
#define TN 128          // nodes per tile in transform1 (8 warps x 16 nodes)

// ---------------- scratch (device globals; no allocation allowed) ----------------
__device__ int     g_cnt[NN * NREL];                     // 2.8 MB  per-(dst,rel) edge count
__device__ int     g_bucket[(size_t)NN * NREL * CAP];    // 44.8 MB src per segment slot
__device__ __half2 g_yh[(size_t)NREL * NN * 32];         // 89.6 MB y[r][node] = x@W1[r] (fp16)
__device__ float   g_z[(size_t)NREL * NN * 2];           // 5.6 MB  z[r][node] (rel-major)
__device__ float   g_hbase[(size_t)NN * 64];             // x @ root1 + bias1

// ---------------- mma helper (m16n8k16 fp16 -> f32) ----------------
__device__ __forceinline__ void mma16816(float& d0, float& d1, float& d2, float& d3,
                                         uint32_t a0, uint32_t a1, uint32_t a2, uint32_t a3,
                                         uint32_t b0, uint32_t b1) {
    asm volatile(
        "mma.sync.aligned.m16n8k16.row.col.f32.f16.f16.f32 "
        "{%0,%1,%2,%3}, {%4,%5,%6,%7}, {%8,%9}, {%0,%1,%2,%3};"
        : "+f"(d0), "+f"(d1), "+f"(d2), "+f"(d3)
        : "r"(a0), "r"(a1), "r"(a2), "r"(a3), "r"(b0), "r"(b1));
}

// ---------------- small kernels ----------------
__global__ void zero_cnt_kernel(int n7q) {
    int i = blockIdx.x * blockDim.x + threadIdx.x;
    if (i < n7q) ((int4*)g_cnt)[i] = make_int4(0, 0, 0, 0);
}

// ---------------- mega kernel 1: scatter | dense1 | transform1 ----------------
__device__ __forceinline__ void scatter_body(const int* __restrict__ ei,
                                             const int* __restrict__ et,
                                             int n, int e, int bid) {
    int i = bid * 256 + threadIdx.x;
    if (i >= e) return;
    int dst = ei[e + i];
    int r   = et[i];
    long seg = (long)dst * NREL + r;
    int idx = atomicAdd(&g_cnt[seg], 1);
    if (idx < CAP) g_bucket[seg * CAP + idx] = ei[i];
}

__device__ __forceinline__ void dense1_body(const float* __restrict__ x,
                                            const float* __restrict__ root1,
                                            const float* __restrict__ bias1,
                                            int n, int bid, char* smem_raw) {
    float (*As)[33] = (float (*)[33])smem_raw;                 // 64 x 33 floats
    float (*Bs)[64] = (float (*)[64])(smem_raw + 64 * 33 * 4); // 32 x 64 floats
    int tid = threadIdx.x;
    int tx = tid & 15, ty = tid >> 4;
    int row0 = bid * 64;
    float acc[4][4];
#pragma unroll
    for (int i = 0; i < 4; i++)
#pragma unroll
        for (int j = 0; j < 4; j++) acc[i][j] = 0.f;

    for (int k0 = 0; k0 < 128; k0 += 32) {
        for (int t = tid; t < 512; t += 256) {          // A tile 64x32
            int m = t >> 3;
            int kk = (t & 7) << 2;
            int row = row0 + m;
            float4 v = make_float4(0.f, 0.f, 0.f, 0.f);
            if (row < n) v = *(const float4*)(x + (size_t)row * 128 + k0 + kk);
            As[m][kk] = v.x; As[m][kk + 1] = v.y; As[m][kk + 2] = v.z; As[m][kk + 3] = v.w;
        }
        for (int t = tid; t < 512; t += 256) {          // B tile 32x64
            int kk = t >> 4;
            int c4 = (t & 15) << 2;
            *(float4*)&Bs[kk][c4] = *(const float4*)(root1 + (size_t)(k0 + kk) * 64 + c4);
        }
        __syncthreads();
#pragma unroll
        for (int kk = 0; kk < 32; kk++) {
            float a0 = As[ty * 4 + 0][kk];
            float a1 = As[ty * 4 + 1][kk];
            float a2 = As[ty * 4 + 2][kk];
            float a3 = As[ty * 4 + 3][kk];
            float4 bv = *(float4*)&Bs[kk][tx * 4];
            acc[0][0] += a0 * bv.x; acc[0][1] += a0 * bv.y; acc[0][2] += a0 * bv.z; acc[0][3] += a0 * bv.w;
            acc[1][0] += a1 * bv.x; acc[1][1] += a1 * bv.y; acc[1][2] += a1 * bv.z; acc[1][3] += a1 * bv.w;
            acc[2][0] += a2 * bv.x; acc[2][1] += a2 * bv.y; acc[2][2] += a2 * bv.z; acc[2][3] += a2 * bv.w;
            acc[3][0] += a3 * bv.x; acc[3][1] += a3 * bv.y; acc[3][2] += a3 * bv.z; acc[3][3] += a3 * bv.w;
        }
        __syncthreads();
    }
    float4 bv = *(const float4*)(bias1 + tx * 4);
#pragma unroll
    for (int rr = 0; rr < 4; rr++) {
        int row = row0 + ty * 4 + rr;
        if (row < n) {
            float4 o;
            o.x = acc[rr][0] + bv.x; o.y = acc[rr][1] + bv.y;
            o.z = acc[rr][2] + bv.z; o.w = acc[rr][3] + bv.w;
            *(float4*)(g_hbase + (size_t)row * 64 + tx * 4) = o;
        }
    }
}

// Tensor-core transform: y[r][node] = x[node] @ W1[r] (block-diag), fp16 in,
// fp32 accum, fp16 out. Warp = 16 nodes; mma.m16n8k16 per (b, khalf, nhalf).
// x tile staged once as fp16 (A-frags preloaded to regs, reused for all 7 r).
// After A-preload the xs smem region is DEAD -> reused as per-warp y staging
// buffer so global y stores are fully-coalesced 128B float4 rows.
#define XS_STRIDE 68    // half2 per x row
#define WT_STRIDE 40    // halves per Wt row
#define XS_BYTES (TN * XS_STRIDE * 4)          // 34816
#define WT_OFF   XS_BYTES                      // 128B-aligned
#define YS_STRIDE 36    // half2 per staged y row (144B)

__device__ __forceinline__ void transform1_body(const float* __restrict__ x,
                                                const float* __restrict__ W1,
                                                int n, int bid, char* smem_raw) {
    __half2* xs = (__half2*)smem_raw;
    __half*  Wt = (__half*)(smem_raw + WT_OFF);
    int node0 = bid * TN;
    int tid  = threadIdx.x;
    int lane = tid & 31;
    int wid  = tid >> 5;
    int nn = min(TN, n - node0);

    // stage x tile as fp16 half2 pairs
    for (int idx = tid; idx < nn * 64; idx += 256) {
        int row = idx >> 6;
        int c   = idx & 63;
        float2 v = *(const float2*)(x + (size_t)(node0 + row) * 128 + c * 2);
        xs[row * XS_STRIDE + c] = __float22half2_rn(v);
    }
    __syncthreads();

    // preload A fragments: lane (g = lane>>2, t = lane&3)
    int g = lane >> 2;
    int t = lane & 3;
    int row0 = wid * 16;
    uint32_t A[4][2][4];
#pragma unroll
    for (int b = 0; b < 4; b++)
#pragma unroll
        for (int ks = 0; ks < 2; ks++) {
            int ci = b * 16 + ks * 8 + t;       // half2 col index
            const uint32_t* r0 = (const uint32_t*)&xs[(row0 + g) * XS_STRIDE + ci];
            const uint32_t* r1 = (const uint32_t*)&xs[(row0 + g + 8) * XS_STRIDE + ci];
            A[b][ks][0] = r0[0];
            A[b][ks][1] = r1[0];
            A[b][ks][2] = r0[4];
            A[b][ks][3] = r1[4];
        }

    // per-warp y staging buffer (aliases the now-dead xs region)
    __half2* ys = (__half2*)smem_raw + (size_t)wid * (16 * YS_STRIDE);
    int valid = min(16, nn - row0);             // nodes this warp owns (may be <=0)

    for (int r = 0; r < NREL; r++) {
        __syncthreads();   // previous relation's Wt reads done (and r=0: A-preload done)
        // stage Wt[b*16+o][i] = (half)W1[r][b][i][o]
        for (int idx = tid; idx < 2048; idx += 256) {
            int b = idx >> 9;
            int i = (idx >> 4) & 31;
            int o = idx & 15;
            float w = W1[(((size_t)r * 4 + b) * 32 + i) * 16 + o];
            Wt[(b * 16 + o) * WT_STRIDE + i] = __float2half_rn(w);
        }
        __syncthreads();

#pragma unroll
        for (int b = 0; b < 4; b++) {
#pragma unroll
            for (int nh = 0; nh < 2; nh++) {
                float d0 = 0.f, d1 = 0.f, d2 = 0.f, d3 = 0.f;
#pragma unroll
                for (int ks = 0; ks < 2; ks++) {
                    const __half* wrow = &Wt[(b * 16 + nh * 8 + g) * WT_STRIDE + ks * 16 + t * 2];
                    uint32_t b0 = *(const uint32_t*)wrow;
                    uint32_t b1 = *(const uint32_t*)(wrow + 8);
                    mma16816(d0, d1, d2, d3,
                             A[b][ks][0], A[b][ks][1], A[b][ks][2], A[b][ks][3],
                             b0, b1);
                }
                int ci = b * 8 + nh * 4 + t;
                ys[g * YS_STRIDE + ci]       = __floats2half2_rn(d0, d1);
                ys[(g + 8) * YS_STRIDE + ci] = __floats2half2_rn(d2, d3);
            }
        }
        __syncwarp();
        // coalesced copy-out: 16 rows x 128B as float4
        float4* ydst = (float4*)(g_yh + ((size_t)r * n + node0 + row0) * 32);
#pragma unroll
        for (int k = 0; k < 4; k++) {
            int idx  = k * 32 + lane;
            int rowi = idx >> 3;
            int f4   = idx & 7;
            if (rowi < valid)
                ydst[rowi * 8 + f4] =
                    *(const float4*)((const char*)ys + rowi * (YS_STRIDE * 4) + f4 * 16);
        }
        __syncwarp();
    }
}

__global__ void __launch_bounds__(256) mega1_kernel(const float* __restrict__ x,
                                                    const int* __restrict__ ei,
                                                    const int* __restrict__ et,
                                                    const float* __restrict__ W1,
                                                    const float* __restrict__ root1,
                                                    const float* __restrict__ bias1,
                                                    int n, int e,
                                                    int nScatter, int nDense) {
    __shared__ __align__(16) char smem_raw[XS_BYTES + 64 * WT_STRIDE * 2];  // ~40 KB
    int bid = blockIdx.x;
    if (bid < nScatter) {
        scatter_body(ei, et, n, e, bid);
    } else if (bid < nScatter + nDense) {
        dense1_body(x, root1, bias1, n, bid - nScatter, smem_raw);
    } else {
        transform1_body(x, W1, n, bid - nScatter - nDense, smem_raw);
    }
}

// ---------------- agg1 + transform2 + root2-partial fused ----------------
// h = relu(hbase + sum_r max_{edges(r,dst)} y[r][src])  (register-only; h is
// never stored -- transform2 and root2 consume it in-register);
// z[r][node] = h @ W2[r];  out[node] = h @ root2 + bias2.
// Epilogue: multi-value butterfly, 16 totals in 16 SHFL.
__global__ void agg1_kernel(const float* __restrict__ comp2,
                            const float* __restrict__ basis2,
                            const float* __restrict__ root2,
                            const float* __restrict__ bias2,
                            float* __restrict__ out, int n) {
    __shared__ float W2s[NREL * 128];
    for (int t = threadIdx.x; t < NREL * 128; t += blockDim.x) {
        int r = t >> 7;
        int rest = t & 127;
        float v = 0.f;
#pragma unroll
        for (int bb = 0; bb < 4; bb++) v += comp2[r * 4 + bb] * basis2[bb * 128 + rest];
        W2s[t] = v;
    }
    __syncthreads();

    int node = (blockIdx.x * blockDim.x + threadIdx.x) >> 5;
    int lane = threadIdx.x & 31;
    if (node >= n) return;
    int myc = (lane < NREL) ? g_cnt[(size_t)node * NREL + lane] : 0;
    const int* bkbase = g_bucket + (size_t)node * NREL * CAP;

    // all 7 bucket rows up-front (independent 64B coalesced loads)
    int row[NREL];
    int sl = lane & (CAP - 1);
#pragma unroll
    for (int r = 0; r < NREL; r++) row[r] = bkbase[r * CAP + sl];

    int c[NREL];
#pragma unroll
    for (int r = 0; r < NREL; r++) c[r] = min(__shfl_sync(0xffffffffu, myc, r), CAP);

    const __half2 NEGINF2 = __float2half2_rn(-CUDART_INF_F);
    // prefetch edge 0 and edge 1 of every relation (up to 14 loads in flight)
    __half2 vA[NREL], vB[NREL];
#pragma unroll
    for (int r = 0; r < NREL; r++) {
        vA[r] = NEGINF2;
        int s0 = __shfl_sync(0xffffffffu, row[r], 0);
        if (c[r] > 0) vA[r] = g_yh[((size_t)r * n + s0) * 32 + lane];
    }
#pragma unroll
    for (int r = 0; r < NREL; r++) {
        vB[r] = NEGINF2;
        int s1 = __shfl_sync(0xffffffffu, row[r], 1);
        if (c[r] > 1) vB[r] = g_yh[((size_t)r * n + s1) * 32 + lane];
    }

    float2 v = *(const float2*)(g_hbase + (size_t)node * 64 + lane * 2);
#pragma unroll
    for (int r = 0; r < NREL; r++) {
        if (c[r] == 0) continue;
        __half2 m = vA[r];
        if (c[r] > 1) m = __hmax2(m, vB[r]);
        const __half2* yb = g_yh + (size_t)r * n * 32 + lane;
        for (int j = 2; j < c[r]; j++) {                // rare tail (P ~ 0.17/rel)
            int s = __shfl_sync(0xffffffffu, row[r], j);
            m = __hmax2(m, yb[(size_t)s * 32]);
        }
        float2 mf = __half22float2(m);
        v.x += mf.x; v.y += mf.y;
    }
    v.x = fmaxf(v.x, 0.f);
    v.y = fmaxf(v.y, 0.f);

    // ---- per-lane partials: 16 targets = (7 rels + root) x 2 channels ----
    float p[16];
#pragma unroll
    for (int s = 0; s < NREL; s++) {
        float4 wv = *(const float4*)&W2s[s * 128 + lane * 4];
        p[s * 2]     = v.x * wv.x + v.y * wv.z;
        p[s * 2 + 1] = v.x * wv.y + v.y * wv.w;
    }
    {
        float4 rw = *(const float4*)(root2 + lane * 4);
        p[14] = v.x * rw.x + v.y * rw.z;
        p[15] = v.x * rw.y + v.y * rw.w;
    }
    // ---- multi-value butterfly: 16 totals in 16 SHFL ----
    float q8[8];
#pragma unroll
    for (int i = 0; i < 8; i++) {
        bool hi = (lane & 16) != 0;
        float send = hi ? p[i] : p[i + 8];
        float recv = __shfl_xor_sync(0xffffffffu, send, 16);
        q8[i] = (hi ? p[i + 8] : p[i]) + recv;
    }
    float q4[4];
#pragma unroll
    for (int i = 0; i < 4; i++) {
        bool hi = (lane & 8) != 0;
        float send = hi ? q8[i] : q8[i + 4];
        float recv = __shfl_xor_sync(0xffffffffu, send, 8);
        q4[i] = (hi ? q8[i + 4] : q8[i]) + recv;
    }
    float q2[2];
#pragma unroll
    for (int i = 0; i < 2; i++) {
        bool hi = (lane & 4) != 0;
        float send = hi ? q4[i] : q4[i + 2];
        float recv = __shfl_xor_sync(0xffffffffu, send, 4);
        q2[i] = (hi ? q4[i + 2] : q4[i]) + recv;
    }
    float q1;
    {
        bool hi = (lane & 2) != 0;
        float send = hi ? q2[0] : q2[1];
        float recv = __shfl_xor_sync(0xffffffffu, send, 2);
        q1 = (hi ? q2[1] : q2[0]) + recv;
    }
    q1 += __shfl_xor_sync(0xffffffffu, q1, 1);
    // lane (bit0==0) holds target: ch = (lane>>1)&1, slot = (lane>>2)&7
    if (!(lane & 1)) {
        int slot = (lane >> 2) & 7;
        int ch   = (lane >> 1) & 1;
        if (slot < NREL) {
            g_z[((size_t)slot * n + node) * 2 + ch] = q1;
        } else {
            out[(size_t)node * 2 + ch] = q1 + bias2[ch];
        }
    }
}

// out[node] += sum_r max_{edges(r,dst)} z[r][src]
// 4 nodes per warp: 8-lane groups, lane&7 = relation (lane&7==7 idle).
__global__ void final_kernel(float* __restrict__ out, int n) {
    int warp = (blockIdx.x * blockDim.x + threadIdx.x) >> 5;
    int lane = threadIdx.x & 31;
    int nl = lane >> 3;          // 0..3 node within warp
    int r  = lane & 7;           // relation (7 = idle)
    int node = warp * 4 + nl;
    float p0 = 0.f, p1 = 0.f;
    if (node < n && r < NREL) {
        size_t seg = (size_t)node * NREL + r;
        int c = min(g_cnt[seg], CAP);
        if (c > 0) {
            const int* bk = g_bucket + seg * CAP;
            const float* zb = g_z + (size_t)r * n * 2;
            float m0 = -CUDART_INF_F, m1 = -CUDART_INF_F;
            for (int j = 0; j < c; j++) {
                int src = bk[j];
                float2 zz = *(const float2*)(zb + (size_t)src * 2);
                m0 = fmaxf(m0, zz.x); m1 = fmaxf(m1, zz.y);
            }
            p0 = m0; p1 = m1;
        }
    }
#pragma unroll
    for (int off = 4; off >= 1; off >>= 1) {
        p0 += __shfl_down_sync(0xffffffffu, p0, off, 8);
        p1 += __shfl_down_sync(0xffffffffu, p1, off, 8);
    }
    if (r == 0 && node < n) {
        float2 o = *(float2*)(out + (size_t)node * 2);
        o.x += p0; o.y += p1;
        *(float2*)(out + (size_t)node * 2) = o;
    }
}

// ---------------- launch ----------------
extern "C" void kernel_launch(void* const* d_in, const int* in_sizes, int n_in,
                              void* d_out, int out_size) {
    const float* x      = (const float*)d_in[0];
    const int*   ei     = (const int*)  d_in[1];
    const int*   et     = (const int*)  d_in[2];
    const float* W1     = (const float*)d_in[3];
    const float* root1  = (const float*)d_in[4];
    const float* bias1  = (const float*)d_in[5];
    const float* comp2  = (const float*)d_in[6];
    const float* basis2 = (const float*)d_in[7];
    const float* root2  = (const float*)d_in[8];
    const float* bias2  = (const float*)d_in[9];
    float* out = (float*)d_out;

    int n = in_sizes[0] / 128;   // 100000
    int e = in_sizes[2];         // 1000000

    int n7 = n * NREL;
    zero_cnt_kernel<<<(n7 / 4 + 255) / 256, 256>>>(n7 / 4);

    int nScatter = (e + 255) / 256;
    int nDense   = (n + 63) / 64;
    int nTrans   = (n + TN - 1) / TN;
    mega1_kernel<<<nScatter + nDense + nTrans, 256>>>(x, ei, et, W1, root1, bias1,
                                                      n, e, nScatter, nDense);

    int warpBlocks = (n * 32 + 255) / 256;
    agg1_kernel<<<warpBlocks, 256>>>(comp2, basis2, root2, bias2, out, n);

    int finalBlocks = ((n + 3) / 4 * 32 + 255) / 256;
    final_kernel<<<finalBlocks, 256>>>(out, n);
}

// round 14
// speedup vs baseline: 1.0765x; 1.0036x over previous
#include <cuda_runtime.h>
#include <cuda_fp16.h>
#include <cstdint>
#include <math_constants.h>

// Problem constants (fixed by the dataset)
#define NN 100000
#define EE 1000000
#define NREL 7
#define CAP 16          // max edges per (dst,rel) segment; Poisson(1.43), max over 700K segs ~ 12
#define TN 128          // nodes per tile in transform1 (8 warps x 16 nodes)

// ---------------- scratch (device globals; no allocation allowed) ----------------
// g_cnt starts zeroed (.bss) and is re-zeroed by final_kernel every call, so no
// separate zeroing launch is needed (deterministic across replays by induction).
__device__ int     g_cnt[NN * NREL];                     // 2.8 MB  per-(dst,rel) edge count
__device__ int     g_bucket[(size_t)NN * NREL * CAP];    // 44.8 MB src per segment slot
__device__ __half2 g_yh[(size_t)NREL * NN * 32];         // 89.6 MB y[r][node] = x@W1[r] (fp16)
__device__ float   g_z[(size_t)NREL * NN * 2];           // 5.6 MB  z[r][node] (rel-major)
__device__ float   g_hbase[(size_t)NN * 64];             // x @ root1 + bias1

// ---------------- mma helper (m16n8k16 fp16 -> f32) ----------------
__device__ __forceinline__ void mma16816(float& d0, float& d1, float& d2, float& d3,
                                         uint32_t a0, uint32_t a1, uint32_t a2, uint32_t a3,
                                         uint32_t b0, uint32_t b1) {
    asm volatile(
        "mma.sync.aligned.m16n8k16.row.col.f32.f16.f16.f32 "
        "{%0,%1,%2,%3}, {%4,%5,%6,%7}, {%8,%9}, {%0,%1,%2,%3};"
        : "+f"(d0), "+f"(d1), "+f"(d2), "+f"(d3)
        : "r"(a0), "r"(a1), "r"(a2), "r"(a3), "r"(b0), "r"(b1));
}

// ---------------- mega kernel 1: scatter | dense1 | transform1 ----------------
__device__ __forceinline__ void scatter_body(const int* __restrict__ ei,
                                             const int* __restrict__ et,
                                             int n, int e, int bid) {
    int i = bid * 256 + threadIdx.x;
    if (i >= e) return;
    int dst = ei[e + i];
    int r   = et[i];
    long seg = (long)dst * NREL + r;
    int idx = atomicAdd(&g_cnt[seg], 1);
    if (idx < CAP) g_bucket[seg * CAP + idx] = ei[i];
}

__device__ __forceinline__ void dense1_body(const float* __restrict__ x,
                                            const float* __restrict__ root1,
                                            const float* __restrict__ bias1,
                                            int n, int bid, char* smem_raw) {
    float (*As)[33] = (float (*)[33])smem_raw;                 // 64 x 33 floats
    float (*Bs)[64] = (float (*)[64])(smem_raw + 64 * 33 * 4); // 32 x 64 floats
    int tid = threadIdx.x;
    int tx = tid & 15, ty = tid >> 4;
    int row0 = bid * 64;
    float acc[4][4];
#pragma unroll
    for (int i = 0; i < 4; i++)
#pragma unroll
        for (int j = 0; j < 4; j++) acc[i][j] = 0.f;

    for (int k0 = 0; k0 < 128; k0 += 32) {
        for (int t = tid; t < 512; t += 256) {          // A tile 64x32
            int m = t >> 3;
            int kk = (t & 7) << 2;
            int row = row0 + m;
            float4 v = make_float4(0.f, 0.f, 0.f, 0.f);
            if (row < n) v = *(const float4*)(x + (size_t)row * 128 + k0 + kk);
            As[m][kk] = v.x; As[m][kk + 1] = v.y; As[m][kk + 2] = v.z; As[m][kk + 3] = v.w;
        }
        for (int t = tid; t < 512; t += 256) {          // B tile 32x64
            int kk = t >> 4;
            int c4 = (t & 15) << 2;
            *(float4*)&Bs[kk][c4] = *(const float4*)(root1 + (size_t)(k0 + kk) * 64 + c4);
        }
        __syncthreads();
#pragma unroll
        for (int kk = 0; kk < 32; kk++) {
            float a0 = As[ty * 4 + 0][kk];
            float a1 = As[ty * 4 + 1][kk];
            float a2 = As[ty * 4 + 2][kk];
            float a3 = As[ty * 4 + 3][kk];
            float4 bv = *(float4*)&Bs[kk][tx * 4];
            acc[0][0] += a0 * bv.x; acc[0][1] += a0 * bv.y; acc[0][2] += a0 * bv.z; acc[0][3] += a0 * bv.w;
            acc[1][0] += a1 * bv.x; acc[1][1] += a1 * bv.y; acc[1][2] += a1 * bv.z; acc[1][3] += a1 * bv.w;
            acc[2][0] += a2 * bv.x; acc[2][1] += a2 * bv.y; acc[2][2] += a2 * bv.z; acc[2][3] += a2 * bv.w;
            acc[3][0] += a3 * bv.x; acc[3][1] += a3 * bv.y; acc[3][2] += a3 * bv.z; acc[3][3] += a3 * bv.w;
        }
        __syncthreads();
    }
    float4 bv = *(const float4*)(bias1 + tx * 4);
#pragma unroll
    for (int rr = 0; rr < 4; rr++) {
        int row = row0 + ty * 4 + rr;
        if (row < n) {
            float4 o;
            o.x = acc[rr][0] + bv.x; o.y = acc[rr][1] + bv.y;
            o.z = acc[rr][2] + bv.z; o.w = acc[rr][3] + bv.w;
            *(float4*)(g_hbase + (size_t)row * 64 + tx * 4) = o;
        }
    }
}

// Tensor-core transform: y[r][node] = x[node] @ W1[r] (block-diag), fp16 in,
// fp32 accum, fp16 out. Warp = 16 nodes; mma.m16n8k16 per (b, khalf, nhalf).
// x tile staged once as fp16 (A-frags preloaded to regs, reused for all 7 r).
// After A-preload the xs smem region is DEAD -> reused as per-warp y staging
// buffer so global y stores are fully-coalesced 128B float4 rows.
#define XS_STRIDE 68    // half2 per x row
#define WT_STRIDE 40    // halves per Wt row
#define XS_BYTES (TN * XS_STRIDE * 4)          // 34816
#define WT_OFF   XS_BYTES                      // 128B-aligned
#define YS_STRIDE 36    // half2 per staged y row (144B)

__device__ __forceinline__ void transform1_body(const float* __restrict__ x,
                                                const float* __restrict__ W1,
                                                int n, int bid, char* smem_raw) {
    __half2* xs = (__half2*)smem_raw;
    __half*  Wt = (__half*)(smem_raw + WT_OFF);
    int node0 = bid * TN;
    int tid  = threadIdx.x;
    int lane = tid & 31;
    int wid  = tid >> 5;
    int nn = min(TN, n - node0);

    // stage x tile as fp16 half2 pairs
    for (int idx = tid; idx < nn * 64; idx += 256) {
        int row = idx >> 6;
        int c   = idx & 63;
        float2 v = *(const float2*)(x + (size_t)(node0 + row) * 128 + c * 2);
        xs[row * XS_STRIDE + c] = __float22half2_rn(v);
    }
    __syncthreads();

    // preload A fragments: lane (g = lane>>2, t = lane&3)
    int g = lane >> 2;
    int t = lane & 3;
    int row0 = wid * 16;
    uint32_t A[4][2][4];
#pragma unroll
    for (int b = 0; b < 4; b++)
#pragma unroll
        for (int ks = 0; ks < 2; ks++) {
            int ci = b * 16 + ks * 8 + t;       // half2 col index
            const uint32_t* r0 = (const uint32_t*)&xs[(row0 + g) * XS_STRIDE + ci];
            const uint32_t* r1 = (const uint32_t*)&xs[(row0 + g + 8) * XS_STRIDE + ci];
            A[b][ks][0] = r0[0];
            A[b][ks][1] = r1[0];
            A[b][ks][2] = r0[4];
            A[b][ks][3] = r1[4];
        }

    // per-warp y staging buffer (aliases the now-dead xs region)
    __half2* ys = (__half2*)smem_raw + (size_t)wid * (16 * YS_STRIDE);
    int valid = min(16, nn - row0);             // nodes this warp owns (may be <=0)

    for (int r = 0; r < NREL; r++) {
        __syncthreads();   // previous relation's Wt reads done (and r=0: A-preload done)
        // stage Wt[b*16+o][i] = (half)W1[r][b][i][o]
        for (int idx = tid; idx < 2048; idx += 256) {
            int b = idx >> 9;
            int i = (idx >> 4) & 31;
            int o = idx & 15;
            float w = W1[(((size_t)r * 4 + b) * 32 + i) * 16 + o];
            Wt[(b * 16 + o) * WT_STRIDE + i] = __float2half_rn(w);
        }
        __syncthreads();

#pragma unroll
        for (int b = 0; b < 4; b++) {
#pragma unroll
            for (int nh = 0; nh < 2; nh++) {
                float d0 = 0.f, d1 = 0.f, d2 = 0.f, d3 = 0.f;
#pragma unroll
                for (int ks = 0; ks < 2; ks++) {
                    const __half* wrow = &Wt[(b * 16 + nh * 8 + g) * WT_STRIDE + ks * 16 + t * 2];
                    uint32_t b0 = *(const uint32_t*)wrow;
                    uint32_t b1 = *(const uint32_t*)(wrow + 8);
                    mma16816(d0, d1, d2, d3,
                             A[b][ks][0], A[b][ks][1], A[b][ks][2], A[b][ks][3],
                             b0, b1);
                }
                int ci = b * 8 + nh * 4 + t;
                ys[g * YS_STRIDE + ci]       = __floats2half2_rn(d0, d1);
                ys[(g + 8) * YS_STRIDE + ci] = __floats2half2_rn(d2, d3);
            }
        }
        __syncwarp();
        // coalesced copy-out: 16 rows x 128B as float4
        float4* ydst = (float4*)(g_yh + ((size_t)r * n + node0 + row0) * 32);
#pragma unroll
        for (int k = 0; k < 4; k++) {
            int idx  = k * 32 + lane;
            int rowi = idx >> 3;
            int f4   = idx & 7;
            if (rowi < valid)
                ydst[rowi * 8 + f4] =
                    *(const float4*)((const char*)ys + rowi * (YS_STRIDE * 4) + f4 * 16);
        }
        __syncwarp();
    }
}

__global__ void __launch_bounds__(256) mega1_kernel(const float* __restrict__ x,
                                                    const int* __restrict__ ei,
                                                    const int* __restrict__ et,
                                                    const float* __restrict__ W1,
                                                    const float* __restrict__ root1,
                                                    const float* __restrict__ bias1,
                                                    int n, int e,
                                                    int nScatter, int nDense) {
    __shared__ __align__(16) char smem_raw[XS_BYTES + 64 * WT_STRIDE * 2];  // ~40 KB
    int bid = blockIdx.x;
    if (bid < nScatter) {
        scatter_body(ei, et, n, e, bid);
    } else if (bid < nScatter + nDense) {
        dense1_body(x, root1, bias1, n, bid - nScatter, smem_raw);
    } else {
        transform1_body(x, W1, n, bid - nScatter - nDense, smem_raw);
    }
}

// ---------------- agg1 + transform2 + root2-partial fused ----------------
// h = relu(hbase + sum_r max_{edges(r,dst)} y[r][src])  (register-only);
// z[r][node] = h @ W2[r];  out[node] = h @ root2 + bias2.
// Bucket rows read 8-wide (32B); slots 8..15 pre-loaded once per relation,
// warp-uniformly predicated on c>8 (P ~ 5e-4) -- no branch in the tail loop.
// Epilogue: multi-value butterfly, 16 totals in 16 SHFL.
__global__ void agg1_kernel(const float* __restrict__ comp2,
                            const float* __restrict__ basis2,
                            const float* __restrict__ root2,
                            const float* __restrict__ bias2,
                            float* __restrict__ out, int n) {
    __shared__ float W2s[NREL * 128];
    for (int t = threadIdx.x; t < NREL * 128; t += blockDim.x) {
        int r = t >> 7;
        int rest = t & 127;
        float v = 0.f;
#pragma unroll
        for (int bb = 0; bb < 4; bb++) v += comp2[r * 4 + bb] * basis2[bb * 128 + rest];
        W2s[t] = v;
    }
    __syncthreads();

    int node = (blockIdx.x * blockDim.x + threadIdx.x) >> 5;
    int lane = threadIdx.x & 31;
    if (node >= n) return;
    int myc = (lane < NREL) ? g_cnt[(size_t)node * NREL + lane] : 0;
    const int* bkbase = g_bucket + (size_t)node * NREL * CAP;

    // 8-wide bucket rows (32B per segment; lanes 8..31 broadcast-duplicate)
    int row[NREL];
    int sl = lane & 7;
#pragma unroll
    for (int r = 0; r < NREL; r++) row[r] = bkbase[r * CAP + sl];

    int c[NREL];
#pragma unroll
    for (int r = 0; r < NREL; r++) c[r] = min(__shfl_sync(0xffffffffu, myc, r), CAP);

    // slots 8..15, loaded only when needed (warp-uniform predicate, ultra-rare)
    int rowHi[NREL];
#pragma unroll
    for (int r = 0; r < NREL; r++)
        rowHi[r] = (c[r] > 8) ? bkbase[r * CAP + 8 + sl] : 0;

    const __half2 NEGINF2 = __float2half2_rn(-CUDART_INF_F);
    // prefetch edge 0 and edge 1 of every relation (up to 14 loads in flight)
    __half2 vA[NREL], vB[NREL];
#pragma unroll
    for (int r = 0; r < NREL; r++) {
        vA[r] = NEGINF2;
        int s0 = __shfl_sync(0xffffffffu, row[r], 0);
        if (c[r] > 0) vA[r] = g_yh[((size_t)r * n + s0) * 32 + lane];
    }
#pragma unroll
    for (int r = 0; r < NREL; r++) {
        vB[r] = NEGINF2;
        int s1 = __shfl_sync(0xffffffffu, row[r], 1);
        if (c[r] > 1) vB[r] = g_yh[((size_t)r * n + s1) * 32 + lane];
    }

    float2 v = *(const float2*)(g_hbase + (size_t)node * 64 + lane * 2);
#pragma unroll
    for (int r = 0; r < NREL; r++) {
        if (c[r] == 0) continue;
        __half2 m = vA[r];
        if (c[r] > 1) m = __hmax2(m, vB[r]);
        const __half2* yb = g_yh + (size_t)r * n * 32 + lane;
        for (int j = 2; j < c[r]; j++) {                // rare tail (P ~ 0.17/rel)
            int s = __shfl_sync(0xffffffffu, (j < 8) ? row[r] : rowHi[r], j & 15);
            m = __hmax2(m, yb[(size_t)s * 32]);
        }
        float2 mf = __half22float2(m);
        v.x += mf.x; v.y += mf.y;
    }
    v.x = fmaxf(v.x, 0.f);
    v.y = fmaxf(v.y, 0.f);

    // ---- per-lane partials: 16 targets = (7 rels + root) x 2 channels ----
    float p[16];
#pragma unroll
    for (int s = 0; s < NREL; s++) {
        float4 wv = *(const float4*)&W2s[s * 128 + lane * 4];
        p[s * 2]     = v.x * wv.x + v.y * wv.z;
        p[s * 2 + 1] = v.x * wv.y + v.y * wv.w;
    }
    {
        float4 rw = *(const float4*)(root2 + lane * 4);
        p[14] = v.x * rw.x + v.y * rw.z;
        p[15] = v.x * rw.y + v.y * rw.w;
    }
    // ---- multi-value butterfly: 16 totals in 16 SHFL ----
    float q8[8];
#pragma unroll
    for (int i = 0; i < 8; i++) {
        bool hi = (lane & 16) != 0;
        float send = hi ? p[i] : p[i + 8];
        float recv = __shfl_xor_sync(0xffffffffu, send, 16);
        q8[i] = (hi ? p[i + 8] : p[i]) + recv;
    }
    float q4[4];
#pragma unroll
    for (int i = 0; i < 4; i++) {
        bool hi = (lane & 8) != 0;
        float send = hi ? q8[i] : q8[i + 4];
        float recv = __shfl_xor_sync(0xffffffffu, send, 8);
        q4[i] = (hi ? q8[i + 4] : q8[i]) + recv;
    }
    float q2[2];
#pragma unroll
    for (int i = 0; i < 2; i++) {
        bool hi = (lane & 4) != 0;
        float send = hi ? q4[i] : q4[i + 2];
        float recv = __shfl_xor_sync(0xffffffffu, send, 4);
        q2[i] = (hi ? q4[i + 2] : q4[i]) + recv;
    }
    float q1;
    {
        bool hi = (lane & 2) != 0;
        float send = hi ? q2[0] : q2[1];
        float recv = __shfl_xor_sync(0xffffffffu, send, 2);
        q1 = (hi ? q2[1] : q2[0]) + recv;
    }
    q1 += __shfl_xor_sync(0xffffffffu, q1, 1);
    // lane (bit0==0) holds target: ch = (lane>>1)&1, slot = (lane>>2)&7
    if (!(lane & 1)) {
        int slot = (lane >> 2) & 7;
        int ch   = (lane >> 1) & 1;
        if (slot < NREL) {
            g_z[((size_t)slot * n + node) * 2 + ch] = q1;
        } else {
            out[(size_t)node * 2 + ch] = q1 + bias2[ch];
        }
    }
}

// out[node] += sum_r max_{edges(r,dst)} z[r][src];  then zero g_cnt for the
// next call (replaces the standalone zeroing kernel).
// 4 nodes per warp: 8-lane groups, lane&7 = relation (lane&7==7 idle).
__global__ void final_kernel(float* __restrict__ out, int n) {
    int warp = (blockIdx.x * blockDim.x + threadIdx.x) >> 5;
    int lane = threadIdx.x & 31;
    int nl = lane >> 3;          // 0..3 node within warp
    int r  = lane & 7;           // relation (7 = idle)
    int node = warp * 4 + nl;
    float p0 = 0.f, p1 = 0.f;
    bool active = (node < n && r < NREL);
    size_t seg = active ? ((size_t)node * NREL + r) : 0;
    if (active) {
        int c = min(g_cnt[seg], CAP);
        if (c > 0) {
            const int* bk = g_bucket + seg * CAP;
            const float* zb = g_z + (size_t)r * n * 2;
            float m0 = -CUDART_INF_F, m1 = -CUDART_INF_F;
            for (int j = 0; j < c; j++) {
                int src = bk[j];
                float2 zz = *(const float2*)(zb + (size_t)src * 2);
                m0 = fmaxf(m0, zz.x); m1 = fmaxf(m1, zz.y);
            }
            p0 = m0; p1 = m1;
        }
    }
#pragma unroll
    for (int off = 4; off >= 1; off >>= 1) {
        p0 += __shfl_down_sync(0xffffffffu, p0, off, 8);
        p1 += __shfl_down_sync(0xffffffffu, p1, off, 8);
    }
    if (r == 0 && node < n) {
        float2 o = *(float2*)(out + (size_t)node * 2);
        o.x += p0; o.y += p1;
        *(float2*)(out + (size_t)node * 2) = o;
    }
    // re-zero counters for the next kernel_launch call
    if (active) g_cnt[seg] = 0;
}

// ---------------- launch ----------------
extern "C" void kernel_launch(void* const* d_in, const int* in_sizes, int n_in,
                              void* d_out, int out_size) {
    const float* x      = (const float*)d_in[0];
    const int*   ei     = (const int*)  d_in[1];
    const int*   et     = (const int*)  d_in[2];
    const float* W1     = (const float*)d_in[3];
    const float* root1  = (const float*)d_in[4];
    const float* bias1  = (const float*)d_in[5];
    const float* comp2  = (const float*)d_in[6];
    const float* basis2 = (const float*)d_in[7];
    const float* root2  = (const float*)d_in[8];
    const float* bias2  = (const float*)d_in[9];
    float* out = (float*)d_out;

    int n = in_sizes[0] / 128;   // 100000
    int e = in_sizes[2];         // 1000000

    int nScatter = (e + 255) / 256;
    int nDense   = (n + 63) / 64;
    int nTrans   = (n + TN - 1) / TN;
    mega1_kernel<<<nScatter + nDense + nTrans, 256>>>(x, ei, et, W1, root1, bias1,
                                                      n, e, nScatter, nDense);

    int warpBlocks = (n * 32 + 255) / 256;
    agg1_kernel<<<warpBlocks, 256>>>(comp2, basis2, root2, bias2, out, n);

    int finalBlocks = ((n + 3) / 4 * 32 + 255) / 256;
    final_kernel<<<finalBlocks, 256>>>(out, n);
}

// round 15
// speedup vs baseline: 1.1433x; 1.0620x over previous
#include <cuda_runtime.h>
#include <cuda_fp16.h>
#include <cstdint>
#include <math_constants.h>

// Problem constants (fixed by the dataset)
#define NN 100000
#define EE 1000000
#define NREL 7
#define CAP 16          // max edges per (dst,rel) segment; Poisson(1.43), max over 700K segs ~ 12
#define TN 128          // nodes per tile in transform1 (8 warps x 16 nodes)

// ---------------- scratch (device globals; no allocation allowed) ----------------
// g_cnt starts zeroed (.bss) and is re-zeroed by final_kernel every call, so no
// separate zeroing launch is needed (deterministic across replays by induction).
__device__ int     g_cnt[NN * NREL];                     // 2.8 MB  per-(dst,rel) edge count
__device__ int     g_bucket[(size_t)NN * NREL * CAP];    // 44.8 MB src per segment slot
__device__ __half2 g_yh[(size_t)NREL * NN * 32];         // 89.6 MB y[r][node] = x@W1[r] (fp16)
__device__ float   g_z[(size_t)NREL * NN * 2];           // 5.6 MB  z[r][node] (rel-major)
__device__ float   g_hbase[(size_t)NN * 64];             // x @ root1 + bias1

#define WT_STRIDE 40    // halves per Wt row (bank-safe)
// fp16 weight images in the exact smem staging layout (built by wconv_kernel)
__device__ __align__(16) __half g_wt16[NREL * 64 * WT_STRIDE]; // [r][(b*16+o)][i]
__device__ __align__(16) __half g_rt16[4 * 64 * WT_STRIDE];    // [kb][n][kk]  root1 chunks

// ---------------- mma helper (m16n8k16 fp16 -> f32) ----------------
__device__ __forceinline__ void mma16816(float& d0, float& d1, float& d2, float& d3,
                                         uint32_t a0, uint32_t a1, uint32_t a2, uint32_t a3,
                                         uint32_t b0, uint32_t b1) {
    asm volatile(
        "mma.sync.aligned.m16n8k16.row.col.f32.f16.f16.f32 "
        "{%0,%1,%2,%3}, {%4,%5,%6,%7}, {%8,%9}, {%0,%1,%2,%3};"
        : "+f"(d0), "+f"(d1), "+f"(d2), "+f"(d3)
        : "r"(a0), "r"(a1), "r"(a2), "r"(a3), "r"(b0), "r"(b1));
}

// ---------------- weight pre-conversion (fp32 -> fp16 smem-image layout) ----------
__global__ void wconv_kernel(const float* __restrict__ W1,
                             const float* __restrict__ root1) {
    int i = blockIdx.x * 256 + threadIdx.x;
    if (i < NREL * 64 * 32) {                       // Wt image: [r][b*16+o][k]
        int r   = i / 2048;
        int rem = i % 2048;
        int row = rem >> 5;                         // b*16 + o
        int k   = rem & 31;
        int b = row >> 4, o = row & 15;
        g_wt16[(r * 64 + row) * WT_STRIDE + k] =
            __float2half_rn(W1[(((size_t)r * 4 + b) * 32 + k) * 16 + o]);
    }
    int j = i - NREL * 64 * 32;
    if (j >= 0 && j < 4 * 64 * 32) {                // RT image: [kb][n][kk]
        int kb  = j / 2048;
        int rem = j % 2048;
        int nr  = rem >> 5;
        int kk  = rem & 31;
        g_rt16[(kb * 64 + nr) * WT_STRIDE + kk] =
            __float2half_rn(root1[(kb * 32 + kk) * 64 + nr]);
    }
}

// ---------------- mega kernel 1: scatter | transform1(+hbase) ----------------
__device__ __forceinline__ void scatter_body(const int* __restrict__ ei,
                                             const int* __restrict__ et,
                                             int n, int e, int bid) {
    int i = bid * 256 + threadIdx.x;
    if (i >= e) return;
    int dst = ei[e + i];
    int r   = et[i];
    long seg = (long)dst * NREL + r;
    int idx = atomicAdd(&g_cnt[seg], 1);
    if (idx < CAP) g_bucket[seg * CAP + idx] = ei[i];
}

// Tensor-core transform: per 128-node tile computes BOTH
//   hbase[node] = x @ root1 + bias1 (fp32 store)   and
//   y[r][node]  = x @ W1[r] (block-diag, fp16 store)  for all 7 relations,
// reusing one set of A-fragments (x as fp16, all K=128, in registers).
// Weights staged per-chunk from prebuilt fp16 global images (straight memcpy).
#define XS_STRIDE 68    // half2 per x row
#define XS_BYTES (TN * XS_STRIDE * 4)          // 34816
#define WT_OFF   XS_BYTES                      // 16B-aligned
#define YS_STRIDE 36    // half2 per staged y row (144B)

__device__ __forceinline__ void transform1_body(const float* __restrict__ x,
                                                const float* __restrict__ bias1,
                                                int n, int bid, char* smem_raw) {
    __half2* xs = (__half2*)smem_raw;
    __half*  Wt = (__half*)(smem_raw + WT_OFF);
    int node0 = bid * TN;
    int tid  = threadIdx.x;
    int lane = tid & 31;
    int wid  = tid >> 5;
    int nn = min(TN, n - node0);

    // stage x tile as fp16 (float4 loads; warp covers a full 512B row -> coalesced)
    for (int idx = tid; idx < nn * 32; idx += 256) {
        int row = idx >> 5;
        int q   = idx & 31;
        float4 v = *(const float4*)(x + (size_t)(node0 + row) * 128 + q * 4);
        xs[row * XS_STRIDE + q * 2]     = __floats2half2_rn(v.x, v.y);
        xs[row * XS_STRIDE + q * 2 + 1] = __floats2half2_rn(v.z, v.w);
    }
    __syncthreads();

    // preload A fragments: lane (g = lane>>2, t = lane&3); A[b][ks] covers
    // k = b*32 + ks*16 .. +15 -> all K=128.
    int g = lane >> 2;
    int t = lane & 3;
    int row0 = wid * 16;
    uint32_t A[4][2][4];
#pragma unroll
    for (int b = 0; b < 4; b++)
#pragma unroll
        for (int ks = 0; ks < 2; ks++) {
            int ci = b * 16 + ks * 8 + t;
            const uint32_t* r0 = (const uint32_t*)&xs[(row0 + g) * XS_STRIDE + ci];
            const uint32_t* r1 = (const uint32_t*)&xs[(row0 + g + 8) * XS_STRIDE + ci];
            A[b][ks][0] = r0[0];
            A[b][ks][1] = r1[0];
            A[b][ks][2] = r0[4];
            A[b][ks][3] = r1[4];
        }

    // ---- root path: hbase = x @ root1 + bias1 (dense, 4 K-chunks) ----
    float dr[8][4];
#pragma unroll
    for (int nt = 0; nt < 8; nt++)
#pragma unroll
        for (int q = 0; q < 4; q++) dr[nt][q] = 0.f;

#pragma unroll
    for (int kb = 0; kb < 4; kb++) {
        __syncthreads();   // Wt region reuse (kb=0: also guards A-preload reads of xs? A done)
        for (int t4 = tid; t4 < 320; t4 += 256)
            ((float4*)Wt)[t4] = ((const float4*)g_rt16)[kb * 320 + t4];
        __syncthreads();
#pragma unroll
        for (int nt = 0; nt < 8; nt++) {
#pragma unroll
            for (int ks = 0; ks < 2; ks++) {
                const __half* wrow = &Wt[(nt * 8 + g) * WT_STRIDE + ks * 16 + t * 2];
                uint32_t b0 = *(const uint32_t*)wrow;
                uint32_t b1 = *(const uint32_t*)(wrow + 8);
                mma16816(dr[nt][0], dr[nt][1], dr[nt][2], dr[nt][3],
                         A[kb][ks][0], A[kb][ks][1], A[kb][ks][2], A[kb][ks][3],
                         b0, b1);
            }
        }
    }
    // bias + store hbase (fp32). D-frag: lane holds (row g, col t*2..) and (row g+8).
    {
        int nodeA = node0 + row0 + g;
        bool okA = (nodeA < n) && (row0 + g < nn);
        bool okB = (nodeA + 8 < n) && (row0 + g + 8 < nn);
        float* hb = g_hbase + (size_t)nodeA * 64 + t * 2;
#pragma unroll
        for (int nt = 0; nt < 8; nt++) {
            float2 bv = *(const float2*)(bias1 + nt * 8 + t * 2);
            if (okA) *(float2*)(hb + nt * 8) =
                make_float2(dr[nt][0] + bv.x, dr[nt][1] + bv.y);
            if (okB) *(float2*)(hb + (size_t)8 * 64 + nt * 8) =
                make_float2(dr[nt][2] + bv.x, dr[nt][3] + bv.y);
        }
    }

    // per-warp y staging buffer (aliases the now-dead xs region)
    __half2* ys = (__half2*)smem_raw + (size_t)wid * (16 * YS_STRIDE);
    int valid = min(16, nn - row0);             // nodes this warp owns (may be <=0)

    // ---- relation path: y[r] = x @ W1[r] (block-diag) ----
    for (int r = 0; r < NREL; r++) {
        __syncthreads();   // previous chunk's Wt reads done
        for (int t4 = tid; t4 < 320; t4 += 256)
            ((float4*)Wt)[t4] = ((const float4*)g_wt16)[r * 320 + t4];
        __syncthreads();

#pragma unroll
        for (int b = 0; b < 4; b++) {
#pragma unroll
            for (int nh = 0; nh < 2; nh++) {
                float d0 = 0.f, d1 = 0.f, d2 = 0.f, d3 = 0.f;
#pragma unroll
                for (int ks = 0; ks < 2; ks++) {
                    const __half* wrow = &Wt[(b * 16 + nh * 8 + g) * WT_STRIDE + ks * 16 + t * 2];
                    uint32_t b0 = *(const uint32_t*)wrow;
                    uint32_t b1 = *(const uint32_t*)(wrow + 8);
                    mma16816(d0, d1, d2, d3,
                             A[b][ks][0], A[b][ks][1], A[b][ks][2], A[b][ks][3],
                             b0, b1);
                }
                int ci = b * 8 + nh * 4 + t;
                ys[g * YS_STRIDE + ci]       = __floats2half2_rn(d0, d1);
                ys[(g + 8) * YS_STRIDE + ci] = __floats2half2_rn(d2, d3);
            }
        }
        __syncwarp();
        // coalesced copy-out: 16 rows x 128B as float4
        float4* ydst = (float4*)(g_yh + ((size_t)r * n + node0 + row0) * 32);
#pragma unroll
        for (int k = 0; k < 4; k++) {
            int idx  = k * 32 + lane;
            int rowi = idx >> 3;
            int f4   = idx & 7;
            if (rowi < valid)
                ydst[rowi * 8 + f4] =
                    *(const float4*)((const char*)ys + rowi * (YS_STRIDE * 4) + f4 * 16);
        }
        __syncwarp();
    }
}

__global__ void __launch_bounds__(256) mega1_kernel(const float* __restrict__ x,
                                                    const int* __restrict__ ei,
                                                    const int* __restrict__ et,
                                                    const float* __restrict__ bias1,
                                                    int n, int e, int nScatter) {
    __shared__ __align__(16) char smem_raw[XS_BYTES + 64 * WT_STRIDE * 2];  // ~40 KB
    int bid = blockIdx.x;
    if (bid < nScatter) {
        scatter_body(ei, et, n, e, bid);
    } else {
        transform1_body(x, bias1, n, bid - nScatter, smem_raw);
    }
}

// ---------------- agg1 + transform2 + root2-partial fused ----------------
// h = relu(hbase + sum_r max_{edges(r,dst)} y[r][src])  (register-only);
// z[r][node] = h @ W2[r];  out[node] = h @ root2 + bias2.
// Bucket rows read 8-wide (32B); slots 8..15 pre-loaded once per relation,
// warp-uniformly predicated on c>8 (P ~ 5e-4) -- no branch in the tail loop.
// Epilogue: multi-value butterfly, 16 totals in 16 SHFL.
__global__ void agg1_kernel(const float* __restrict__ comp2,
                            const float* __restrict__ basis2,
                            const float* __restrict__ root2,
                            const float* __restrict__ bias2,
                            float* __restrict__ out, int n) {
    __shared__ float W2s[NREL * 128];
    for (int t = threadIdx.x; t < NREL * 128; t += blockDim.x) {
        int r = t >> 7;
        int rest = t & 127;
        float v = 0.f;
#pragma unroll
        for (int bb = 0; bb < 4; bb++) v += comp2[r * 4 + bb] * basis2[bb * 128 + rest];
        W2s[t] = v;
    }
    __syncthreads();

    int node = (blockIdx.x * blockDim.x + threadIdx.x) >> 5;
    int lane = threadIdx.x & 31;
    if (node >= n) return;
    int myc = (lane < NREL) ? g_cnt[(size_t)node * NREL + lane] : 0;
    const int* bkbase = g_bucket + (size_t)node * NREL * CAP;

    // 8-wide bucket rows (32B per segment; lanes 8..31 broadcast-duplicate)
    int row[NREL];
    int sl = lane & 7;
#pragma unroll
    for (int r = 0; r < NREL; r++) row[r] = bkbase[r * CAP + sl];

    int c[NREL];
#pragma unroll
    for (int r = 0; r < NREL; r++) c[r] = min(__shfl_sync(0xffffffffu, myc, r), CAP);

    // slots 8..15, loaded only when needed (warp-uniform predicate, ultra-rare)
    int rowHi[NREL];
#pragma unroll
    for (int r = 0; r < NREL; r++)
        rowHi[r] = (c[r] > 8) ? bkbase[r * CAP + 8 + sl] : 0;

    const __half2 NEGINF2 = __float2half2_rn(-CUDART_INF_F);
    // prefetch edge 0 and edge 1 of every relation (up to 14 loads in flight)
    __half2 vA[NREL], vB[NREL];
#pragma unroll
    for (int r = 0; r < NREL; r++) {
        vA[r] = NEGINF2;
        int s0 = __shfl_sync(0xffffffffu, row[r], 0);
        if (c[r] > 0) vA[r] = g_yh[((size_t)r * n + s0) * 32 + lane];
    }
#pragma unroll
    for (int r = 0; r < NREL; r++) {
        vB[r] = NEGINF2;
        int s1 = __shfl_sync(0xffffffffu, row[r], 1);
        if (c[r] > 1) vB[r] = g_yh[((size_t)r * n + s1) * 32 + lane];
    }

    float2 v = *(const float2*)(g_hbase + (size_t)node * 64 + lane * 2);
#pragma unroll
    for (int r = 0; r < NREL; r++) {
        if (c[r] == 0) continue;
        __half2 m = vA[r];
        if (c[r] > 1) m = __hmax2(m, vB[r]);
        const __half2* yb = g_yh + (size_t)r * n * 32 + lane;
        for (int j = 2; j < c[r]; j++) {                // rare tail (P ~ 0.17/rel)
            int s = __shfl_sync(0xffffffffu, (j < 8) ? row[r] : rowHi[r], j & 15);
            m = __hmax2(m, yb[(size_t)s * 32]);
        }
        float2 mf = __half22float2(m);
        v.x += mf.x; v.y += mf.y;
    }
    v.x = fmaxf(v.x, 0.f);
    v.y = fmaxf(v.y, 0.f);

    // ---- per-lane partials: 16 targets = (7 rels + root) x 2 channels ----
    float p[16];
#pragma unroll
    for (int s = 0; s < NREL; s++) {
        float4 wv = *(const float4*)&W2s[s * 128 + lane * 4];
        p[s * 2]     = v.x * wv.x + v.y * wv.z;
        p[s * 2 + 1] = v.x * wv.y + v.y * wv.w;
    }
    {
        float4 rw = *(const float4*)(root2 + lane * 4);
        p[14] = v.x * rw.x + v.y * rw.z;
        p[15] = v.x * rw.y + v.y * rw.w;
    }
    // ---- multi-value butterfly: 16 totals in 16 SHFL ----
    float q8[8];
#pragma unroll
    for (int i = 0; i < 8; i++) {
        bool hi = (lane & 16) != 0;
        float send = hi ? p[i] : p[i + 8];
        float recv = __shfl_xor_sync(0xffffffffu, send, 16);
        q8[i] = (hi ? p[i + 8] : p[i]) + recv;
    }
    float q4[4];
#pragma unroll
    for (int i = 0; i < 4; i++) {
        bool hi = (lane & 8) != 0;
        float send = hi ? q8[i] : q8[i + 4];
        float recv = __shfl_xor_sync(0xffffffffu, send, 8);
        q4[i] = (hi ? q8[i + 4] : q8[i]) + recv;
    }
    float q2[2];
#pragma unroll
    for (int i = 0; i < 2; i++) {
        bool hi = (lane & 4) != 0;
        float send = hi ? q4[i] : q4[i + 2];
        float recv = __shfl_xor_sync(0xffffffffu, send, 4);
        q2[i] = (hi ? q4[i + 2] : q4[i]) + recv;
    }
    float q1;
    {
        bool hi = (lane & 2) != 0;
        float send = hi ? q2[0] : q2[1];
        float recv = __shfl_xor_sync(0xffffffffu, send, 2);
        q1 = (hi ? q2[1] : q2[0]) + recv;
    }
    q1 += __shfl_xor_sync(0xffffffffu, q1, 1);
    // lane (bit0==0) holds target: ch = (lane>>1)&1, slot = (lane>>2)&7
    if (!(lane & 1)) {
        int slot = (lane >> 2) & 7;
        int ch   = (lane >> 1) & 1;
        if (slot < NREL) {
            g_z[((size_t)slot * n + node) * 2 + ch] = q1;
        } else {
            out[(size_t)node * 2 + ch] = q1 + bias2[ch];
        }
    }
}

// out[node] += sum_r max_{edges(r,dst)} z[r][src];  then zero g_cnt for the
// next call (replaces the standalone zeroing kernel).
// 4 nodes per warp: 8-lane groups, lane&7 = relation (lane&7==7 idle).
__global__ void final_kernel(float* __restrict__ out, int n) {
    int warp = (blockIdx.x * blockDim.x + threadIdx.x) >> 5;
    int lane = threadIdx.x & 31;
    int nl = lane >> 3;          // 0..3 node within warp
    int r  = lane & 7;           // relation (7 = idle)
    int node = warp * 4 + nl;
    float p0 = 0.f, p1 = 0.f;
    bool active = (node < n && r < NREL);
    size_t seg = active ? ((size_t)node * NREL + r) : 0;
    if (active) {
        int c = min(g_cnt[seg], CAP);
        if (c > 0) {
            const int* bk = g_bucket + seg * CAP;
            const float* zb = g_z + (size_t)r * n * 2;
            float m0 = -CUDART_INF_F, m1 = -CUDART_INF_F;
            for (int j = 0; j < c; j++) {
                int src = bk[j];
                float2 zz = *(const float2*)(zb + (size_t)src * 2);
                m0 = fmaxf(m0, zz.x); m1 = fmaxf(m1, zz.y);
            }
            p0 = m0; p1 = m1;
        }
    }
#pragma unroll
    for (int off = 4; off >= 1; off >>= 1) {
        p0 += __shfl_down_sync(0xffffffffu, p0, off, 8);
        p1 += __shfl_down_sync(0xffffffffu, p1, off, 8);
    }
    if (r == 0 && node < n) {
        float2 o = *(float2*)(out + (size_t)node * 2);
        o.x += p0; o.y += p1;
        *(float2*)(out + (size_t)node * 2) = o;
    }
    // re-zero counters for the next kernel_launch call
    if (active) g_cnt[seg] = 0;
}

// ---------------- launch ----------------
extern "C" void kernel_launch(void* const* d_in, const int* in_sizes, int n_in,
                              void* d_out, int out_size) {
    const float* x      = (const float*)d_in[0];
    const int*   ei     = (const int*)  d_in[1];
    const int*   et     = (const int*)  d_in[2];
    const float* W1     = (const float*)d_in[3];
    const float* root1  = (const float*)d_in[4];
    const float* bias1  = (const float*)d_in[5];
    const float* comp2  = (const float*)d_in[6];
    const float* basis2 = (const float*)d_in[7];
    const float* root2  = (const float*)d_in[8];
    const float* bias2  = (const float*)d_in[9];
    float* out = (float*)d_out;

    int n = in_sizes[0] / 128;   // 100000
    int e = in_sizes[2];         // 1000000

    // fp16 weight images (Wt: 7*2048 elems, RT: 4*2048 elems -> 88 blocks)
    wconv_kernel<<<88, 256>>>(W1, root1);

    int nScatter = (e + 255) / 256;
    int nTrans   = (n + TN - 1) / TN;
    mega1_kernel<<<nScatter + nTrans, 256>>>(x, ei, et, bias1, n, e, nScatter);

    int warpBlocks = (n * 32 + 255) / 256;
    agg1_kernel<<<warpBlocks, 256>>>(comp2, basis2, root2, bias2, out, n);

    int finalBlocks = ((n + 3) / 4 * 32 + 255) / 256;
    final_kernel<<<finalBlocks, 256>>>(out, n);
}

// round 17
// speedup vs baseline: 1.2107x; 1.0589x over previous
#include <cuda_runtime.h>
#include <cuda_fp16.h>
#include <cstdint>
#include <math_constants.h>

// Problem constants (fixed by the dataset)
#define NN 100000
#define EE 1000000
#define NREL 7
#define CAP 16          // max edges per (dst,rel) segment; Poisson(1.43), max over 700K segs ~ 12
#define TN 128          // nodes per tile in transform1 (8 warps x 16 nodes)

// ---------------- scratch (device globals; no allocation allowed) ----------------
// g_cnt starts zeroed (.bss) and is re-zeroed by final_kernel every call, so no
// separate zeroing launch is needed (deterministic across replays by induction).
__device__ int     g_cnt[NN * NREL];                     // 2.8 MB  per-(dst,rel) edge count
__device__ int     g_bucket[(size_t)NN * NREL * CAP];    // 44.8 MB src per segment slot
__device__ __half2 g_yh[(size_t)NREL * NN * 32];         // 89.6 MB y[r][node] = x@W1[r] (fp16)
__device__ float   g_z[(size_t)NREL * NN * 2];           // 5.6 MB  z[r][node] (rel-major)
__device__ float   g_hbase[(size_t)NN * 64];             // x @ root1 + bias1

#define WT_STRIDE 40    // halves per Wt row (bank-safe)
// fp16 weight images in the exact smem staging layout (built by wconv_kernel)
__device__ __align__(16) __half g_wt16[NREL * 64 * WT_STRIDE]; // [r][(b*16+o)][i]
__device__ __align__(16) __half g_rt16[4 * 64 * WT_STRIDE];    // [kb][n][kk]  root1 chunks

// ---------------- mma helper (m16n8k16 fp16 -> f32) ----------------
__device__ __forceinline__ void mma16816(float& d0, float& d1, float& d2, float& d3,
                                         uint32_t a0, uint32_t a1, uint32_t a2, uint32_t a3,
                                         uint32_t b0, uint32_t b1) {
    asm volatile(
        "mma.sync.aligned.m16n8k16.row.col.f32.f16.f16.f32 "
        "{%0,%1,%2,%3}, {%4,%5,%6,%7}, {%8,%9}, {%0,%1,%2,%3};"
        : "+f"(d0), "+f"(d1), "+f"(d2), "+f"(d3)
        : "r"(a0), "r"(a1), "r"(a2), "r"(a3), "r"(b0), "r"(b1));
}

// ---------------- weight pre-conversion (fp32 -> fp16 smem-image layout) ----------
__global__ void wconv_kernel(const float* __restrict__ W1,
                             const float* __restrict__ root1) {
    int i = blockIdx.x * 256 + threadIdx.x;
    if (i < NREL * 64 * 32) {                       // Wt image: [r][b*16+o][k]
        int r   = i / 2048;
        int rem = i % 2048;
        int row = rem >> 5;                         // b*16 + o
        int k   = rem & 31;
        int b = row >> 4, o = row & 15;
        g_wt16[(r * 64 + row) * WT_STRIDE + k] =
            __float2half_rn(W1[(((size_t)r * 4 + b) * 32 + k) * 16 + o]);
    }
    int j = i - NREL * 64 * 32;
    if (j >= 0 && j < 4 * 64 * 32) {                // RT image: [kb][n][kk]
        int kb  = j / 2048;
        int rem = j % 2048;
        int nr  = rem >> 5;
        int kk  = rem & 31;
        g_rt16[(kb * 64 + nr) * WT_STRIDE + kk] =
            __float2half_rn(root1[(kb * 32 + kk) * 64 + nr]);
    }
}

// ---------------- mega kernel 1: transform1(+hbase) | scatter ----------------
__device__ __forceinline__ void scatter_body(const int* __restrict__ ei,
                                             const int* __restrict__ et,
                                             int n, int e, int bid) {
    int i = bid * 256 + threadIdx.x;
    if (i >= e) return;
    int dst = ei[e + i];
    int r   = et[i];
    long seg = (long)dst * NREL + r;
    int idx = atomicAdd(&g_cnt[seg], 1);
    if (idx < CAP) g_bucket[seg * CAP + idx] = ei[i];
}

// Tensor-core transform: per 128-node tile computes BOTH
//   hbase[node] = x @ root1 + bias1 (fp32 store)   and
//   y[r][node]  = x @ W1[r] (block-diag, fp16 store)  for all 7 relations,
// reusing one set of A-fragments (x as fp16, all K=128, in registers).
// 11 weight chunks (4 root + 7 relation) stream through a DOUBLE-BUFFERED
// 2x5KB Wt area: chunk i+1 loads while chunk i computes; 1 sync per chunk.
// (Resubmit of R15 proposal; prior bench hit an infra "device busy" failure.)
#define XS_STRIDE 68    // half2 per x row
#define XS_BYTES (TN * XS_STRIDE * 4)          // 34816
#define WT_OFF   XS_BYTES                      // 16B-aligned
#define WT_BYTES (64 * WT_STRIDE * 2)          // 5120 per buffer
#define YS_STRIDE 36    // half2 per staged y row (144B)

__device__ __forceinline__ void transform1_body(const float* __restrict__ x,
                                                const float* __restrict__ bias1,
                                                int n, int bid, char* smem_raw) {
    __half2* xs = (__half2*)smem_raw;
    __half* WtBuf0 = (__half*)(smem_raw + WT_OFF);
    __half* WtBuf1 = (__half*)(smem_raw + WT_OFF + WT_BYTES);
    int node0 = bid * TN;
    int tid  = threadIdx.x;
    int lane = tid & 31;
    int wid  = tid >> 5;
    int nn = min(TN, n - node0);

    // stage x tile as fp16 (float4 loads; warp covers a full 512B row -> coalesced)
    for (int idx = tid; idx < nn * 32; idx += 256) {
        int row = idx >> 5;
        int q   = idx & 31;
        float4 v = *(const float4*)(x + (size_t)(node0 + row) * 128 + q * 4);
        xs[row * XS_STRIDE + q * 2]     = __floats2half2_rn(v.x, v.y);
        xs[row * XS_STRIDE + q * 2 + 1] = __floats2half2_rn(v.z, v.w);
    }
    // preload chunk 0 (root kb=0) into buffer 0 (disjoint from xs)
    for (int t4 = tid; t4 < 320; t4 += 256)
        ((float4*)WtBuf0)[t4] = ((const float4*)g_rt16)[t4];
    __syncthreads();

    // preload A fragments: lane (g = lane>>2, t = lane&3); A[b][ks] covers
    // k = b*32 + ks*16 .. +15 -> all K=128.
    int g = lane >> 2;
    int t = lane & 3;
    int row0 = wid * 16;
    uint32_t A[4][2][4];
#pragma unroll
    for (int b = 0; b < 4; b++)
#pragma unroll
        for (int ks = 0; ks < 2; ks++) {
            int ci = b * 16 + ks * 8 + t;
            const uint32_t* r0 = (const uint32_t*)&xs[(row0 + g) * XS_STRIDE + ci];
            const uint32_t* r1 = (const uint32_t*)&xs[(row0 + g + 8) * XS_STRIDE + ci];
            A[b][ks][0] = r0[0];
            A[b][ks][1] = r1[0];
            A[b][ks][2] = r0[4];
            A[b][ks][3] = r1[4];
        }

    float dr[8][4];
#pragma unroll
    for (int nt = 0; nt < 8; nt++)
#pragma unroll
        for (int q = 0; q < 4; q++) dr[nt][q] = 0.f;

    // per-warp y staging buffer (aliases the xs region; first written at chunk 4,
    // i.e. after >=4 block-wide syncs -> all A-preloads complete)
    __half2* ys = (__half2*)smem_raw + (size_t)wid * (16 * YS_STRIDE);
    int valid = min(16, nn - row0);             // nodes this warp owns (may be <=0)

    // ---- pipelined chunk loop: i<4 root (kb=i), i>=4 relation (r=i-4) ----
#pragma unroll
    for (int i = 0; i < 11; i++) {
        const __half* Wt = (i & 1) ? WtBuf1 : WtBuf0;
        if (i < 10) {   // prefetch next chunk into the other buffer
            const float4* src = (i + 1 < 4) ? (const float4*)g_rt16 + (i + 1) * 320
                                            : (const float4*)g_wt16 + (i - 3) * 320;
            float4* dst = (float4*)((i & 1) ? WtBuf0 : WtBuf1);
            for (int t4 = tid; t4 < 320; t4 += 256) dst[t4] = src[t4];
        }
        if (i < 4) {
            // root chunk: accumulate into dr
#pragma unroll
            for (int nt = 0; nt < 8; nt++) {
#pragma unroll
                for (int ks = 0; ks < 2; ks++) {
                    const __half* wrow = &Wt[(nt * 8 + g) * WT_STRIDE + ks * 16 + t * 2];
                    uint32_t b0 = *(const uint32_t*)wrow;
                    uint32_t b1 = *(const uint32_t*)(wrow + 8);
                    mma16816(dr[nt][0], dr[nt][1], dr[nt][2], dr[nt][3],
                             A[i][ks][0], A[i][ks][1], A[i][ks][2], A[i][ks][3],
                             b0, b1);
                }
            }
            if (i == 3) {   // bias + store hbase (fp32)
                int nodeA = node0 + row0 + g;
                bool okA = (row0 + g < nn);
                bool okB = (row0 + g + 8 < nn);
                float* hb = g_hbase + (size_t)nodeA * 64 + t * 2;
#pragma unroll
                for (int nt = 0; nt < 8; nt++) {
                    float2 bv = *(const float2*)(bias1 + nt * 8 + t * 2);
                    if (okA) *(float2*)(hb + nt * 8) =
                        make_float2(dr[nt][0] + bv.x, dr[nt][1] + bv.y);
                    if (okB) *(float2*)(hb + (size_t)8 * 64 + nt * 8) =
                        make_float2(dr[nt][2] + bv.x, dr[nt][3] + bv.y);
                }
            }
        } else {
            // relation chunk r = i-4: y[r] = x @ W1[r] (block-diag)
            int r = i - 4;
#pragma unroll
            for (int b = 0; b < 4; b++) {
#pragma unroll
                for (int nh = 0; nh < 2; nh++) {
                    float d0 = 0.f, d1 = 0.f, d2 = 0.f, d3 = 0.f;
#pragma unroll
                    for (int ks = 0; ks < 2; ks++) {
                        const __half* wrow = &Wt[(b * 16 + nh * 8 + g) * WT_STRIDE + ks * 16 + t * 2];
                        uint32_t b0 = *(const uint32_t*)wrow;
                        uint32_t b1 = *(const uint32_t*)(wrow + 8);
                        mma16816(d0, d1, d2, d3,
                                 A[b][ks][0], A[b][ks][1], A[b][ks][2], A[b][ks][3],
                                 b0, b1);
                    }
                    int ci = b * 8 + nh * 4 + t;
                    ys[g * YS_STRIDE + ci]       = __floats2half2_rn(d0, d1);
                    ys[(g + 8) * YS_STRIDE + ci] = __floats2half2_rn(d2, d3);
                }
            }
            __syncwarp();
            // coalesced copy-out: 16 rows x 128B as float4
            float4* ydst = (float4*)(g_yh + ((size_t)r * n + node0 + row0) * 32);
#pragma unroll
            for (int k = 0; k < 4; k++) {
                int idx  = k * 32 + lane;
                int rowi = idx >> 3;
                int f4   = idx & 7;
                if (rowi < valid)
                    ydst[rowi * 8 + f4] =
                        *(const float4*)((const char*)ys + rowi * (YS_STRIDE * 4) + f4 * 16);
            }
        }
        __syncthreads();
    }
}

__global__ void __launch_bounds__(256) mega1_kernel(const float* __restrict__ x,
                                                    const int* __restrict__ ei,
                                                    const int* __restrict__ et,
                                                    const float* __restrict__ bias1,
                                                    int n, int e, int nTrans) {
    __shared__ __align__(16) char smem_raw[XS_BYTES + 2 * WT_BYTES];  // ~44 KB
    int bid = blockIdx.x;
    if (bid < nTrans) {      // long blocks first (longest-job-first scheduling)
        transform1_body(x, bias1, n, bid, smem_raw);
    } else {
        scatter_body(ei, et, n, e, bid - nTrans);
    }
}

// ---------------- agg1 + transform2 + root2-partial fused ----------------
// h = relu(hbase + sum_r max_{edges(r,dst)} y[r][src])  (register-only);
// z[r][node] = h @ W2[r];  out[node] = h @ root2 + bias2.
// Bucket rows read 8-wide (32B); edges 0-2 of every relation prefetched
// up-front (up to 21 independent loads in flight); serial tail only for c>3.
// Epilogue: multi-value butterfly, 16 totals in 16 SHFL.
__global__ void agg1_kernel(const float* __restrict__ comp2,
                            const float* __restrict__ basis2,
                            const float* __restrict__ root2,
                            const float* __restrict__ bias2,
                            float* __restrict__ out, int n) {
    __shared__ float W2s[NREL * 128];
    for (int t = threadIdx.x; t < NREL * 128; t += blockDim.x) {
        int r = t >> 7;
        int rest = t & 127;
        float v = 0.f;
#pragma unroll
        for (int bb = 0; bb < 4; bb++) v += comp2[r * 4 + bb] * basis2[bb * 128 + rest];
        W2s[t] = v;
    }
    __syncthreads();

    int node = (blockIdx.x * blockDim.x + threadIdx.x) >> 5;
    int lane = threadIdx.x & 31;
    if (node >= n) return;
    int myc = (lane < NREL) ? g_cnt[(size_t)node * NREL + lane] : 0;
    const int* bkbase = g_bucket + (size_t)node * NREL * CAP;

    // 8-wide bucket rows (32B per segment; lanes 8..31 broadcast-duplicate)
    int row[NREL];
    int sl = lane & 7;
#pragma unroll
    for (int r = 0; r < NREL; r++) row[r] = bkbase[r * CAP + sl];

    int c[NREL];
#pragma unroll
    for (int r = 0; r < NREL; r++) c[r] = min(__shfl_sync(0xffffffffu, myc, r), CAP);

    // slots 8..15, loaded only when needed (warp-uniform predicate, ultra-rare)
    int rowHi[NREL];
#pragma unroll
    for (int r = 0; r < NREL; r++)
        rowHi[r] = (c[r] > 8) ? bkbase[r * CAP + 8 + sl] : 0;

    const __half2 NEGINF2 = __float2half2_rn(-CUDART_INF_F);
    // prefetch edges 0,1,2 of every relation (independent loads, max MLP)
    __half2 vA[NREL], vB[NREL], vC[NREL];
#pragma unroll
    for (int r = 0; r < NREL; r++) {
        vA[r] = NEGINF2;
        int s0 = __shfl_sync(0xffffffffu, row[r], 0);
        if (c[r] > 0) vA[r] = g_yh[((size_t)r * n + s0) * 32 + lane];
    }
#pragma unroll
    for (int r = 0; r < NREL; r++) {
        vB[r] = NEGINF2;
        int s1 = __shfl_sync(0xffffffffu, row[r], 1);
        if (c[r] > 1) vB[r] = g_yh[((size_t)r * n + s1) * 32 + lane];
    }
#pragma unroll
    for (int r = 0; r < NREL; r++) {
        vC[r] = NEGINF2;
        int s2 = __shfl_sync(0xffffffffu, row[r], 2);
        if (c[r] > 2) vC[r] = g_yh[((size_t)r * n + s2) * 32 + lane];
    }

    float2 v = *(const float2*)(g_hbase + (size_t)node * 64 + lane * 2);
#pragma unroll
    for (int r = 0; r < NREL; r++) {
        if (c[r] == 0) continue;
        __half2 m = __hmax2(vA[r], __hmax2(vB[r], vC[r]));
        const __half2* yb = g_yh + (size_t)r * n * 32 + lane;
        for (int j = 3; j < c[r]; j++) {                // rare tail (P ~ 0.06/rel)
            int s = __shfl_sync(0xffffffffu, (j < 8) ? row[r] : rowHi[r], j & 15);
            m = __hmax2(m, yb[(size_t)s * 32]);
        }
        float2 mf = __half22float2(m);
        v.x += mf.x; v.y += mf.y;
    }
    v.x = fmaxf(v.x, 0.f);
    v.y = fmaxf(v.y, 0.f);

    // ---- per-lane partials: 16 targets = (7 rels + root) x 2 channels ----
    float p[16];
#pragma unroll
    for (int s = 0; s < NREL; s++) {
        float4 wv = *(const float4*)&W2s[s * 128 + lane * 4];
        p[s * 2]     = v.x * wv.x + v.y * wv.z;
        p[s * 2 + 1] = v.x * wv.y + v.y * wv.w;
    }
    {
        float4 rw = *(const float4*)(root2 + lane * 4);
        p[14] = v.x * rw.x + v.y * rw.z;
        p[15] = v.x * rw.y + v.y * rw.w;
    }
    // ---- multi-value butterfly: 16 totals in 16 SHFL ----
    float q8[8];
#pragma unroll
    for (int i = 0; i < 8; i++) {
        bool hi = (lane & 16) != 0;
        float send = hi ? p[i] : p[i + 8];
        float recv = __shfl_xor_sync(0xffffffffu, send, 16);
        q8[i] = (hi ? p[i + 8] : p[i]) + recv;
    }
    float q4[4];
#pragma unroll
    for (int i = 0; i < 4; i++) {
        bool hi = (lane & 8) != 0;
        float send = hi ? q8[i] : q8[i + 4];
        float recv = __shfl_xor_sync(0xffffffffu, send, 8);
        q4[i] = (hi ? q8[i + 4] : q8[i]) + recv;
    }
    float q2[2];
#pragma unroll
    for (int i = 0; i < 2; i++) {
        bool hi = (lane & 4) != 0;
        float send = hi ? q4[i] : q4[i + 2];
        float recv = __shfl_xor_sync(0xffffffffu, send, 4);
        q2[i] = (hi ? q4[i + 2] : q4[i]) + recv;
    }
    float q1;
    {
        bool hi = (lane & 2) != 0;
        float send = hi ? q2[0] : q2[1];
        float recv = __shfl_xor_sync(0xffffffffu, send, 2);
        q1 = (hi ? q2[1] : q2[0]) + recv;
    }
    q1 += __shfl_xor_sync(0xffffffffu, q1, 1);
    // lane (bit0==0) holds target: ch = (lane>>1)&1, slot = (lane>>2)&7
    if (!(lane & 1)) {
        int slot = (lane >> 2) & 7;
        int ch   = (lane >> 1) & 1;
        if (slot < NREL) {
            g_z[((size_t)slot * n + node) * 2 + ch] = q1;
        } else {
            out[(size_t)node * 2 + ch] = q1 + bias2[ch];
        }
    }
}

// out[node] += sum_r max_{edges(r,dst)} z[r][src];  then zero g_cnt for the
// next call (replaces the standalone zeroing kernel).
// 4 nodes per warp: 8-lane groups, lane&7 = relation (lane&7==7 idle).
__global__ void final_kernel(float* __restrict__ out, int n) {
    int warp = (blockIdx.x * blockDim.x + threadIdx.x) >> 5;
    int lane = threadIdx.x & 31;
    int nl = lane >> 3;          // 0..3 node within warp
    int r  = lane & 7;           // relation (7 = idle)
    int node = warp * 4 + nl;
    float p0 = 0.f, p1 = 0.f;
    bool active = (node < n && r < NREL);
    size_t seg = active ? ((size_t)node * NREL + r) : 0;
    if (active) {
        int c = min(g_cnt[seg], CAP);
        if (c > 0) {
            const int* bk = g_bucket + seg * CAP;
            const float* zb = g_z + (size_t)r * n * 2;
            float m0 = -CUDART_INF_F, m1 = -CUDART_INF_F;
            for (int j = 0; j < c; j++) {
                int src = bk[j];
                float2 zz = *(const float2*)(zb + (size_t)src * 2);
                m0 = fmaxf(m0, zz.x); m1 = fmaxf(m1, zz.y);
            }
            p0 = m0; p1 = m1;
        }
    }
#pragma unroll
    for (int off = 4; off >= 1; off >>= 1) {
        p0 += __shfl_down_sync(0xffffffffu, p0, off, 8);
        p1 += __shfl_down_sync(0xffffffffu, p1, off, 8);
    }
    if (r == 0 && node < n) {
        float2 o = *(float2*)(out + (size_t)node * 2);
        o.x += p0; o.y += p1;
        *(float2*)(out + (size_t)node * 2) = o;
    }
    // re-zero counters for the next kernel_launch call
    if (active) g_cnt[seg] = 0;
}

// ---------------- launch ----------------
extern "C" void kernel_launch(void* const* d_in, const int* in_sizes, int n_in,
                              void* d_out, int out_size) {
    const float* x      = (const float*)d_in[0];
    const int*   ei     = (const int*)  d_in[1];
    const int*   et     = (const int*)  d_in[2];
    const float* W1     = (const float*)d_in[3];
    const float* root1  = (const float*)d_in[4];
    const float* bias1  = (const float*)d_in[5];
    const float* comp2  = (const float*)d_in[6];
    const float* basis2 = (const float*)d_in[7];
    const float* root2  = (const float*)d_in[8];
    const float* bias2  = (const float*)d_in[9];
    float* out = (float*)d_out;

    int n = in_sizes[0] / 128;   // 100000
    int e = in_sizes[2];         // 1000000

    // fp16 weight images (Wt: 7*2048 elems, RT: 4*2048 elems -> 88 blocks)
    wconv_kernel<<<88, 256>>>(W1, root1);

    int nScatter = (e + 255) / 256;
    int nTrans   = (n + TN - 1) / TN;
    mega1_kernel<<<nScatter + nTrans, 256>>>(x, ei, et, bias1, n, e, nTrans);

    int warpBlocks = (n * 32 + 255) / 256;
    agg1_kernel<<<warpBlocks, 256>>>(comp2, basis2, root2, bias2, out, n);

    int finalBlocks = ((n + 3) / 4 * 32 + 255) / 256;
    final_kernel<<<finalBlocks, 256>>>(out, n);
}